// round 11
// baseline (speedup 1.0000x reference)
#include <cuda_runtime.h>
#include <cuda_bf16.h>
#include <math.h>

#define N_NODES_MAX 100000
#define N_EDGES_MAX 3200000
#define D 64
#define NL 3
#define SCAN_B 256
#define MAX_NB ((N_NODES_MAX + SCAN_B - 1) / SCAN_B + 1)

// ---- device scratch (no allocation allowed). 256B-aligned for vector loads. ----
__device__ __align__(256) float4 g_edges[N_EDGES_MAX];   // {src, w_l0, w_l1, w_l2}
__device__ __align__(256) int   g_deg[N_NODES_MAX];
__device__ __align__(256) int   g_offs[N_NODES_MAX + 1];
__device__ __align__(256) int   g_cur[N_NODES_MAX];
__device__ __align__(256) int   g_aggs[MAX_NB];
__device__ __align__(256) int   g_prefix[MAX_NB];
__device__ __align__(256) int   g_flags[MAX_NB];
__device__ __align__(256) float g_hA[(size_t)N_NODES_MAX * D];
__device__ __align__(256) float g_hB[(size_t)N_NODES_MAX * D];
__device__ __align__(256) __nv_bfloat16 g_xb [(size_t)N_NODES_MAX * D];
__device__ __align__(256) __nv_bfloat16 g_hbA[(size_t)N_NODES_MAX * D];
__device__ __align__(256) __nv_bfloat16 g_hbB[(size_t)N_NODES_MAX * D];
__device__ int g_is64;

// ---------------------------------------------------------------------------
// Kernel 1: init — zero deg + lookback flags; block 0 also probes edge_index
// dtype (int64 little-endian node ids < 2^31 => every odd 32-bit word is 0).
// ---------------------------------------------------------------------------
__global__ void init_kernel(const int* __restrict__ w32, int N, int NB)
{
    int i = blockIdx.x * blockDim.x + threadIdx.x;
    if (i < N) g_deg[i] = 0;
    if (i < NB) g_flags[i] = 0;

    if (blockIdx.x == 0) {
        __shared__ int any;
        if (threadIdx.x == 0) any = 0;
        __syncthreads();
        int acc = 0;
        for (int k = threadIdx.x * 2 + 1; k < 4096; k += blockDim.x * 2)
            acc |= w32[k];
        if (acc) atomicOr(&any, 1);
        __syncthreads();
        if (threadIdx.x == 0) g_is64 = (any == 0) ? 1 : 0;
    }
}

// ---------------------------------------------------------------------------
// Kernel 2: in-degree histogram over dst.
// ---------------------------------------------------------------------------
__global__ void hist_kernel(const void* __restrict__ eidx_raw, int E)
{
    int e = blockIdx.x * blockDim.x + threadIdx.x;
    if (e >= E) return;
    int d;
    if (g_is64) d = (int)((const long long*)eidx_raw)[(size_t)E + e];
    else        d = ((const int*)eidx_raw)[(size_t)E + e];
    atomicAdd(&g_deg[d], 1);
}

// ---------------------------------------------------------------------------
// Kernel 3: single-pass decoupled-lookback exclusive scan of degrees.
// All blocks co-resident (391 blocks << capacity) -> no deadlock.
// ---------------------------------------------------------------------------
__global__ void scan_lookback(int N)
{
    __shared__ int sh[SCAN_B];
    __shared__ int s_prefix;
    const int tid = threadIdx.x;
    const int b   = blockIdx.x;
    const int i   = b * SCAN_B + tid;

    int v = (i < N) ? g_deg[i] : 0;
    sh[tid] = v;
    __syncthreads();
    for (int off = 1; off < SCAN_B; off <<= 1) {
        int a = sh[tid];
        int c = (tid >= off) ? sh[tid - off] : 0;
        __syncthreads();
        sh[tid] = a + c;
        __syncthreads();
    }

    if (tid == 0) {
        int aggregate = sh[SCAN_B - 1];
        volatile int* vflags  = g_flags;
        volatile int* vaggs   = g_aggs;
        volatile int* vprefix = g_prefix;
        vaggs[b] = aggregate;
        if (b == 0) {
            vprefix[0] = 0;
            __threadfence();
            vflags[0] = 2;
            s_prefix = 0;
        } else {
            __threadfence();
            vflags[b] = 1;
            int sum = 0;
            int j = b - 1;
            while (true) {
                int f;
                do { f = vflags[j]; } while (f == 0);
                if (f == 2) { sum += vprefix[j] + vaggs[j]; break; }
                sum += vaggs[j];
                j--;
            }
            vprefix[b] = sum;
            __threadfence();
            vflags[b] = 2;
            s_prefix = sum;
        }
    }
    __syncthreads();

    int run = s_prefix + sh[tid] - v;   // exclusive prefix for element i
    if (i < N) {
        g_offs[i] = run;
        g_cur[i]  = run;
        if (i == N - 1) g_offs[N] = run + v;
    }
}

// ---------------------------------------------------------------------------
// Kernel 4: edge placement into CSR slots + softplus weights (all 3 layers).
// ---------------------------------------------------------------------------
__global__ void place_kernel(const void* __restrict__ eidx_raw,
                             const float* __restrict__ eattr,
                             const float* __restrict__ emlp_w,
                             const float* __restrict__ emlp_b,
                             int E)
{
    int e = blockIdx.x * blockDim.x + threadIdx.x;
    if (e >= E) return;

    int s, d;
    if (g_is64) {
        const long long* p = (const long long*)eidx_raw;
        s = (int)p[e];
        d = (int)p[(size_t)E + e];
    } else {
        const int* p = (const int*)eidx_raw;
        s = p[e];
        d = p[(size_t)E + e];
    }

    const float4 a0 = *(const float4*)(eattr + (size_t)e * 8);
    const float4 a1 = *(const float4*)(eattr + (size_t)e * 8 + 4);

    float sp[NL];
#pragma unroll
    for (int l = 0; l < NL; l++) {
        const float* wp = emlp_w + l * 8;
        float z = emlp_b[l];
        z = fmaf(a0.x, wp[0], z);
        z = fmaf(a0.y, wp[1], z);
        z = fmaf(a0.z, wp[2], z);
        z = fmaf(a0.w, wp[3], z);
        z = fmaf(a1.x, wp[4], z);
        z = fmaf(a1.y, wp[5], z);
        z = fmaf(a1.z, wp[6], z);
        z = fmaf(a1.w, wp[7], z);
        sp[l] = fmaxf(z, 0.f) + log1pf(expf(-fabsf(z)));
    }

    int pos = atomicAdd(&g_cur[d], 1);
    g_edges[pos] = make_float4(__int_as_float(s), sp[0], sp[1], sp[2]);
}

// ---------------------------------------------------------------------------
// Kernel 5: fp32 -> bf16 shadow of x.
// ---------------------------------------------------------------------------
__global__ void f2bf_kernel(const float* __restrict__ in,
                            __nv_bfloat16* __restrict__ out, int n)
{
    int idx = (blockIdx.x * blockDim.x + threadIdx.x) * 4;
    if (idx < n) {
        float4 v = *(const float4*)(in + idx);
        *(__nv_bfloat162*)(out + idx)     = __floats2bfloat162_rn(v.x, v.y);
        *(__nv_bfloat162*)(out + idx + 2) = __floats2bfloat162_rn(v.z, v.w);
    }
}

// ---------------------------------------------------------------------------
__device__ __forceinline__ void cvt_fma8(float* acc, uint4 u, float w)
{
    float2 p;
    p = __bfloat1622float2(*reinterpret_cast<__nv_bfloat162*>(&u.x));
    acc[0] = fmaf(w, p.x, acc[0]); acc[1] = fmaf(w, p.y, acc[1]);
    p = __bfloat1622float2(*reinterpret_cast<__nv_bfloat162*>(&u.y));
    acc[2] = fmaf(w, p.x, acc[2]); acc[3] = fmaf(w, p.y, acc[3]);
    p = __bfloat1622float2(*reinterpret_cast<__nv_bfloat162*>(&u.z));
    acc[4] = fmaf(w, p.x, acc[4]); acc[5] = fmaf(w, p.y, acc[5]);
    p = __bfloat1622float2(*reinterpret_cast<__nv_bfloat162*>(&u.w));
    acc[6] = fmaf(w, p.x, acc[6]); acc[7] = fmaf(w, p.y, acc[7]);
}

// packed f32x2 FMA: d += a*b lane-wise on a register pair (sm_103a FFMA2)
__device__ __forceinline__ void ffma2(unsigned long long& d,
                                      unsigned long long a,
                                      unsigned long long b)
{
    asm("fma.rn.f32x2 %0, %1, %2, %0;" : "+l"(d) : "l"(a), "l"(b));
}
__device__ __forceinline__ unsigned long long pk2(float x, float y)
{
    unsigned long long u;
    asm("mov.b64 %0, {%1, %2};" : "=l"(u) : "f"(x), "f"(y));
    return u;
}
__device__ __forceinline__ float2 upk2(unsigned long long u)
{
    float2 f;
    asm("mov.b64 {%0, %1}, %2;" : "=f"(f.x), "=f"(f.y) : "l"(u));
    return f;
}

// ---------------------------------------------------------------------------
// Fused per-layer kernel. Warp per node r. Gather: 16 edges/warp-pass (MLP=4).
// Epilogue GEMM: u64-packed weights + u64 activation pairs, pure LDS.64 +
// FFMA2 (3 LDS.64 + 2 FFMA2 per 2 k-steps; no register-pair MOV churn).
// ---------------------------------------------------------------------------
template <int L, bool FUSE_FC>
__global__ void __launch_bounds__(256)
layer_kernel(const float* __restrict__ hin,
             const __nv_bfloat16* __restrict__ hin_b,
             float* __restrict__ hout,
             __nv_bfloat16* __restrict__ hout_b,   // may be null
             const float* __restrict__ W,
             const float* __restrict__ bias,
             const float* __restrict__ gamma,
             const float* __restrict__ beta,
             const float* __restrict__ fcW,
             const float* __restrict__ fcb,
             int N)
{
    __shared__ __align__(16) unsigned long long sWp[D / 2][D];  // 16KB packed W
    __shared__ __align__(16) unsigned long long sFp[FUSE_FC ? D / 2 : 1][FUSE_FC ? D : 1];
    __shared__ float sb[D], sg[D], sbt[D], sfb[D];
    __shared__ __align__(16) float sAv[8][D];                   // per-warp act row

    for (int i = threadIdx.x; i < D * D / 2; i += blockDim.x) {
        int k2 = i >> 6;          // 0..31
        int j  = i & 63;          // 0..63
        float2 t = *(const float2*)(W + j * D + 2 * k2);
        sWp[k2][j] = pk2(t.x, t.y);
        if (FUSE_FC) {
            float2 u = *(const float2*)(fcW + j * D + 2 * k2);
            sFp[k2][j] = pk2(u.x, u.y);
        }
    }
    if (threadIdx.x < D) {
        sb[threadIdx.x]  = bias[threadIdx.x];
        sg[threadIdx.x]  = gamma[threadIdx.x];
        sbt[threadIdx.x] = beta[threadIdx.x];
        if (FUSE_FC) sfb[threadIdx.x] = fcb[threadIdx.x];
    }
    __syncthreads();

    const int warp = threadIdx.x >> 5;
    const int lane = threadIdx.x & 31;
    const int f8      = lane & 7;
    const int quarter = lane >> 3;
    const int warps_per_grid = (blockDim.x >> 5) * gridDim.x;
    float* sA = sAv[warp];
    const unsigned long long* sAp = (const unsigned long long*)sAv[warp];

    for (int r = blockIdx.x * (blockDim.x >> 5) + warp; r < N; r += warps_per_grid) {
        const int start = __ldg(g_offs + r);
        const int end   = __ldg(g_offs + r + 1);

        float acc [8] = {0.f, 0.f, 0.f, 0.f, 0.f, 0.f, 0.f, 0.f};
        float acc2[8] = {0.f, 0.f, 0.f, 0.f, 0.f, 0.f, 0.f, 0.f};
        float cw = 0.f, cw2 = 0.f;

        int i = start + quarter;
        for (; i + 12 < end; i += 16) {
            float4 r0 = __ldg(g_edges + i);
            float4 r1 = __ldg(g_edges + i + 4);
            float4 r2 = __ldg(g_edges + i + 8);
            float4 r3 = __ldg(g_edges + i + 12);
            uint4 u0 = __ldg((const uint4*)(hin_b + (size_t)__float_as_int(r0.x) * D) + f8);
            uint4 u1 = __ldg((const uint4*)(hin_b + (size_t)__float_as_int(r1.x) * D) + f8);
            uint4 u2 = __ldg((const uint4*)(hin_b + (size_t)__float_as_int(r2.x) * D) + f8);
            uint4 u3 = __ldg((const uint4*)(hin_b + (size_t)__float_as_int(r3.x) * D) + f8);
            float w0 = (L == 0) ? r0.y : (L == 1) ? r0.z : r0.w;
            float w1 = (L == 0) ? r1.y : (L == 1) ? r1.z : r1.w;
            float w2 = (L == 0) ? r2.y : (L == 1) ? r2.z : r2.w;
            float w3 = (L == 0) ? r3.y : (L == 1) ? r3.z : r3.w;
            cvt_fma8(acc,  u0, w0); cw  += w0;
            cvt_fma8(acc2, u1, w1); cw2 += w1;
            cvt_fma8(acc,  u2, w2); cw  += w2;
            cvt_fma8(acc2, u3, w3); cw2 += w3;
        }
        for (; i < end; i += 4) {
            float4 re = __ldg(g_edges + i);
            float we = (L == 0) ? re.y : (L == 1) ? re.z : re.w;
            uint4 u = __ldg((const uint4*)(hin_b + (size_t)__float_as_int(re.x) * D) + f8);
            cvt_fma8(acc, u, we); cw += we;
        }
#pragma unroll
        for (int j = 0; j < 8; j++) acc[j] += acc2[j];
        cw += cw2;

#pragma unroll
        for (int j = 0; j < 8; j++) {
            acc[j] += __shfl_xor_sync(0xffffffffu, acc[j], 8);
            acc[j] += __shfl_xor_sync(0xffffffffu, acc[j], 16);
        }
#pragma unroll
        for (int o = 16; o > 0; o >>= 1)
            cw += __shfl_xor_sync(0xffffffffu, cw, o);
        cw *= (1.f / 8.f);

        if (lane < 8) {
#pragma unroll
            for (int j = 0; j < 8; j++)
                sA[f8 * 8 + j] = acc[j];
        }
        __syncwarp();

        float hi0 = hin[(size_t)r * D + lane];
        float hi1 = hin[(size_t)r * D + lane + 32];

        float a0 = sA[lane]      - cw * hi0;
        float a1 = sA[lane + 32] - cw * hi1;
        __syncwarp();
        sA[lane]      = a0;
        sA[lane + 32] = a1;
        __syncwarp();

        // packed GEMM: 3 LDS.64 + 2 FFMA2 per 2 k-steps
        unsigned long long p0 = 0ull, p1 = 0ull;
#pragma unroll
        for (int k2 = 0; k2 < D / 2; k2++) {
            unsigned long long a2 = sAp[k2];   // broadcast LDS.64
            ffma2(p0, a2, sWp[k2][lane]);
            ffma2(p1, a2, sWp[k2][lane + 32]);
        }
        float2 q0 = upk2(p0), q1 = upk2(p1);
        float h0 = fmaxf(q0.x + q0.y + sb[lane], 0.f);
        float h1 = fmaxf(q1.x + q1.y + sb[lane + 32], 0.f);

        float s2 = h0 + h1;
        float sq = h0 * h0 + h1 * h1;
#pragma unroll
        for (int o = 16; o > 0; o >>= 1) {
            s2 += __shfl_xor_sync(0xffffffffu, s2, o);
            sq += __shfl_xor_sync(0xffffffffu, sq, o);
        }
        float mu  = s2 * (1.f / D);
        float var = sq * (1.f / D) - mu * mu;
        float inv = rsqrtf(var + 1e-5f);

        float o0 = (h0 - mu) * inv * sg[lane]      + sbt[lane]      + hi0;
        float o1 = (h1 - mu) * inv * sg[lane + 32] + sbt[lane + 32] + hi1;

        if (FUSE_FC) {
            __syncwarp();
            sA[lane]      = o0;
            sA[lane + 32] = o1;
            __syncwarp();
            unsigned long long f0 = 0ull, f1 = 0ull;
#pragma unroll
            for (int k2 = 0; k2 < D / 2; k2++) {
                unsigned long long a2 = sAp[k2];
                ffma2(f0, a2, sFp[k2][lane]);
                ffma2(f1, a2, sFp[k2][lane + 32]);
            }
            float2 g0 = upk2(f0), g1 = upk2(f1);
            hout[(size_t)r * D + lane]      = g0.x + g0.y + sfb[lane];
            hout[(size_t)r * D + lane + 32] = g1.x + g1.y + sfb[lane + 32];
        } else {
            hout[(size_t)r * D + lane]      = o0;
            hout[(size_t)r * D + lane + 32] = o1;
            hout_b[(size_t)r * D + lane]      = __float2bfloat16(o0);
            hout_b[(size_t)r * D + lane + 32] = __float2bfloat16(o1);
        }
        __syncwarp();
    }
}

// ---------------------------------------------------------------------------
extern "C" void kernel_launch(void* const* d_in, const int* in_sizes, int n_in,
                              void* d_out, int out_size)
{
    const float* x      = (const float*)d_in[0];
    const void*  eidx   = d_in[1];
    const float* eattr  = (const float*)d_in[2];
    const float* lin_w  = (const float*)d_in[3];
    const float* lin_b  = (const float*)d_in[4];
    const float* emlp_w = (const float*)d_in[5];
    const float* emlp_b = (const float*)d_in[6];
    const float* gamma  = (const float*)d_in[7];
    const float* beta   = (const float*)d_in[8];
    const float* fc_w   = (const float*)d_in[9];
    const float* fc_b   = (const float*)d_in[10];
    float*       out    = (float*)d_out;

    const int E = in_sizes[1] / 2;
    const int N = in_sizes[0] / D;

    float *hA, *hB;
    __nv_bfloat16 *xb, *hbA, *hbB;
    cudaGetSymbolAddress((void**)&hA,  g_hA);
    cudaGetSymbolAddress((void**)&hB,  g_hB);
    cudaGetSymbolAddress((void**)&xb,  g_xb);
    cudaGetSymbolAddress((void**)&hbA, g_hbA);
    cudaGetSymbolAddress((void**)&hbB, g_hbB);

    // --- build: exactly 5 launches before layer 0 (ncu -s 5 captures L0) ---
    const int NB = (N + SCAN_B - 1) / SCAN_B;
    init_kernel<<<(N + 255) / 256, 256>>>((const int*)eidx, N, NB);
    hist_kernel<<<(E + 255) / 256, 256>>>(eidx, E);
    scan_lookback<<<NB, SCAN_B>>>(N);
    place_kernel<<<(E + 255) / 256, 256>>>(eidx, eattr, emlp_w, emlp_b, E);
    f2bf_kernel<<<(N * D / 4 + 255) / 256, 256>>>(x, xb, N * D);

    // --- layers (fused gather + packed-GEMM + LN + residual) ---
    const int blocks = 2960, threads = 256;

    layer_kernel<0, false><<<blocks, threads>>>(x,  xb,  hA, hbA,
                                                lin_w, lin_b, gamma, beta,
                                                nullptr, nullptr, N);
    layer_kernel<1, false><<<blocks, threads>>>(hA, hbA, hB, hbB,
                                                lin_w + (size_t)D * D, lin_b + D,
                                                gamma + D, beta + D,
                                                nullptr, nullptr, N);
    layer_kernel<2, true><<<blocks, threads>>>(hB, hbB, out, nullptr,
                                               lin_w + (size_t)2 * D * D, lin_b + 2 * D,
                                               gamma + 2 * D, beta + 2 * D,
                                               fc_w, fc_b, N);
}

// round 12
// speedup vs baseline: 1.0334x; 1.0334x over previous
#include <cuda_runtime.h>
#include <cuda_bf16.h>
#include <math.h>

#define N_NODES_MAX 100000
#define N_EDGES_MAX 3200000
#define D 64
#define NL 3
#define SCAN_B 256
#define MAX_NB ((N_NODES_MAX + SCAN_B - 1) / SCAN_B + 1)

// ---- device scratch (no allocation allowed). 256B-aligned for vector loads. ----
__device__ __align__(256) float4 g_edges[N_EDGES_MAX];   // {src, w_l0, w_l1, w_l2}
__device__ __align__(256) int   g_deg[N_NODES_MAX];
__device__ __align__(256) int   g_offs[N_NODES_MAX + 1];
__device__ __align__(256) int   g_cur[N_NODES_MAX];
__device__ __align__(256) int   g_aggs[MAX_NB];
__device__ __align__(256) int   g_prefix[MAX_NB];
__device__ __align__(256) int   g_flags[MAX_NB];
__device__ __align__(256) float g_hA[(size_t)N_NODES_MAX * D];
__device__ __align__(256) float g_hB[(size_t)N_NODES_MAX * D];
__device__ __align__(256) __nv_bfloat16 g_xb [(size_t)N_NODES_MAX * D];
__device__ __align__(256) __nv_bfloat16 g_hbA[(size_t)N_NODES_MAX * D];
__device__ __align__(256) __nv_bfloat16 g_hbB[(size_t)N_NODES_MAX * D];
__device__ int g_is64;

// ---------------------------------------------------------------------------
// Kernel 1: init — zero deg + lookback flags; block 0 also probes edge_index
// dtype (int64 little-endian node ids < 2^31 => every odd 32-bit word is 0).
// ---------------------------------------------------------------------------
__global__ void init_kernel(const int* __restrict__ w32, int N, int NB)
{
    int i = blockIdx.x * blockDim.x + threadIdx.x;
    if (i < N) g_deg[i] = 0;
    if (i < NB) g_flags[i] = 0;

    if (blockIdx.x == 0) {
        __shared__ int any;
        if (threadIdx.x == 0) any = 0;
        __syncthreads();
        int acc = 0;
        for (int k = threadIdx.x * 2 + 1; k < 4096; k += blockDim.x * 2)
            acc |= w32[k];
        if (acc) atomicOr(&any, 1);
        __syncthreads();
        if (threadIdx.x == 0) g_is64 = (any == 0) ? 1 : 0;
    }
}

// ---------------------------------------------------------------------------
// Kernel 2: in-degree histogram over dst.
// ---------------------------------------------------------------------------
__global__ void hist_kernel(const void* __restrict__ eidx_raw, int E)
{
    int e = blockIdx.x * blockDim.x + threadIdx.x;
    if (e >= E) return;
    int d;
    if (g_is64) d = (int)((const long long*)eidx_raw)[(size_t)E + e];
    else        d = ((const int*)eidx_raw)[(size_t)E + e];
    atomicAdd(&g_deg[d], 1);
}

// ---------------------------------------------------------------------------
// Kernel 3: single-pass decoupled-lookback exclusive scan of degrees.
// All 391 blocks co-resident -> no deadlock.
// ---------------------------------------------------------------------------
__global__ void scan_lookback(int N)
{
    __shared__ int sh[SCAN_B];
    __shared__ int s_prefix;
    const int tid = threadIdx.x;
    const int b   = blockIdx.x;
    const int i   = b * SCAN_B + tid;

    int v = (i < N) ? g_deg[i] : 0;
    sh[tid] = v;
    __syncthreads();
    for (int off = 1; off < SCAN_B; off <<= 1) {
        int a = sh[tid];
        int c = (tid >= off) ? sh[tid - off] : 0;
        __syncthreads();
        sh[tid] = a + c;
        __syncthreads();
    }

    if (tid == 0) {
        int aggregate = sh[SCAN_B - 1];
        volatile int* vflags  = g_flags;
        volatile int* vaggs   = g_aggs;
        volatile int* vprefix = g_prefix;
        vaggs[b] = aggregate;
        if (b == 0) {
            vprefix[0] = 0;
            __threadfence();
            vflags[0] = 2;
            s_prefix = 0;
        } else {
            __threadfence();
            vflags[b] = 1;
            int sum = 0;
            int j = b - 1;
            while (true) {
                int f;
                do { f = vflags[j]; } while (f == 0);
                if (f == 2) { sum += vprefix[j] + vaggs[j]; break; }
                sum += vaggs[j];
                j--;
            }
            vprefix[b] = sum;
            __threadfence();
            vflags[b] = 2;
            s_prefix = sum;
        }
    }
    __syncthreads();

    int run = s_prefix + sh[tid] - v;   // exclusive prefix for element i
    if (i < N) {
        g_offs[i] = run;
        g_cur[i]  = run;
        if (i == N - 1) g_offs[N] = run + v;
    }
}

// ---------------------------------------------------------------------------
// Kernel 4: edge placement into CSR slots + softplus weights (all 3 layers).
// ---------------------------------------------------------------------------
__global__ void place_kernel(const void* __restrict__ eidx_raw,
                             const float* __restrict__ eattr,
                             const float* __restrict__ emlp_w,
                             const float* __restrict__ emlp_b,
                             int E)
{
    int e = blockIdx.x * blockDim.x + threadIdx.x;
    if (e >= E) return;

    int s, d;
    if (g_is64) {
        const long long* p = (const long long*)eidx_raw;
        s = (int)p[e];
        d = (int)p[(size_t)E + e];
    } else {
        const int* p = (const int*)eidx_raw;
        s = p[e];
        d = p[(size_t)E + e];
    }

    const float4 a0 = *(const float4*)(eattr + (size_t)e * 8);
    const float4 a1 = *(const float4*)(eattr + (size_t)e * 8 + 4);

    float sp[NL];
#pragma unroll
    for (int l = 0; l < NL; l++) {
        const float* wp = emlp_w + l * 8;
        float z = emlp_b[l];
        z = fmaf(a0.x, wp[0], z);
        z = fmaf(a0.y, wp[1], z);
        z = fmaf(a0.z, wp[2], z);
        z = fmaf(a0.w, wp[3], z);
        z = fmaf(a1.x, wp[4], z);
        z = fmaf(a1.y, wp[5], z);
        z = fmaf(a1.z, wp[6], z);
        z = fmaf(a1.w, wp[7], z);
        sp[l] = fmaxf(z, 0.f) + log1pf(expf(-fabsf(z)));
    }

    int pos = atomicAdd(&g_cur[d], 1);
    g_edges[pos] = make_float4(__int_as_float(s), sp[0], sp[1], sp[2]);
}

// ---------------------------------------------------------------------------
// Kernel 5: fp32 -> bf16 shadow of x.
// ---------------------------------------------------------------------------
__global__ void f2bf_kernel(const float* __restrict__ in,
                            __nv_bfloat16* __restrict__ out, int n)
{
    int idx = (blockIdx.x * blockDim.x + threadIdx.x) * 4;
    if (idx < n) {
        float4 v = *(const float4*)(in + idx);
        *(__nv_bfloat162*)(out + idx)     = __floats2bfloat162_rn(v.x, v.y);
        *(__nv_bfloat162*)(out + idx + 2) = __floats2bfloat162_rn(v.z, v.w);
    }
}

// ---------------------------------------------------------------------------
__device__ __forceinline__ void cvt_fma8(float* acc, uint4 u, float w)
{
    float2 p;
    p = __bfloat1622float2(*reinterpret_cast<__nv_bfloat162*>(&u.x));
    acc[0] = fmaf(w, p.x, acc[0]); acc[1] = fmaf(w, p.y, acc[1]);
    p = __bfloat1622float2(*reinterpret_cast<__nv_bfloat162*>(&u.y));
    acc[2] = fmaf(w, p.x, acc[2]); acc[3] = fmaf(w, p.y, acc[3]);
    p = __bfloat1622float2(*reinterpret_cast<__nv_bfloat162*>(&u.z));
    acc[4] = fmaf(w, p.x, acc[4]); acc[5] = fmaf(w, p.y, acc[5]);
    p = __bfloat1622float2(*reinterpret_cast<__nv_bfloat162*>(&u.w));
    acc[6] = fmaf(w, p.x, acc[6]); acc[7] = fmaf(w, p.y, acc[7]);
}

// ---------------------------------------------------------------------------
// Fused per-layer kernel (verified-best R9 configuration).
// Warp per node r. Gather: 16 edges/warp-pass (MLP=4 per 8-lane quarter).
// Epilogue GEMM: shuffle-broadcast a, smem weights sW[j][k] (conflict-free
// via +1 pad), 2 outputs per lane.
// ---------------------------------------------------------------------------
template <int L, bool FUSE_FC>
__global__ void __launch_bounds__(256)
layer_kernel(const float* __restrict__ hin,
             const __nv_bfloat16* __restrict__ hin_b,
             float* __restrict__ hout,
             __nv_bfloat16* __restrict__ hout_b,   // may be null
             const float* __restrict__ W,
             const float* __restrict__ bias,
             const float* __restrict__ gamma,
             const float* __restrict__ beta,
             const float* __restrict__ fcW,
             const float* __restrict__ fcb,
             int N)
{
    __shared__ float sW[D][D + 1];
    __shared__ float sF[FUSE_FC ? D : 1][FUSE_FC ? (D + 1) : 1];
    __shared__ float sb[D], sg[D], sbt[D], sfb[D];
    __shared__ float sA[8][D];   // 8 warps per block

    for (int i = threadIdx.x; i < D * D; i += blockDim.x) {
        sW[i >> 6][i & 63] = W[i];
        if (FUSE_FC) sF[i >> 6][i & 63] = fcW[i];
    }
    if (threadIdx.x < D) {
        sb[threadIdx.x]  = bias[threadIdx.x];
        sg[threadIdx.x]  = gamma[threadIdx.x];
        sbt[threadIdx.x] = beta[threadIdx.x];
        if (FUSE_FC) sfb[threadIdx.x] = fcb[threadIdx.x];
    }
    __syncthreads();

    const int warp = threadIdx.x >> 5;
    const int lane = threadIdx.x & 31;
    const int f8      = lane & 7;    // which 16B (8-bf16) chunk of the 128B row
    const int quarter = lane >> 3;   // which of 4 concurrent edges
    const int warps_per_grid = (blockDim.x >> 5) * gridDim.x;

    for (int r = blockIdx.x * (blockDim.x >> 5) + warp; r < N; r += warps_per_grid) {
        const int start = __ldg(g_offs + r);
        const int end   = __ldg(g_offs + r + 1);

        float acc [8] = {0.f, 0.f, 0.f, 0.f, 0.f, 0.f, 0.f, 0.f};
        float acc2[8] = {0.f, 0.f, 0.f, 0.f, 0.f, 0.f, 0.f, 0.f};
        float cw = 0.f, cw2 = 0.f;

        int i = start + quarter;
        // 4 edges in flight per quarter (16 per warp pass)
        for (; i + 12 < end; i += 16) {
            float4 r0 = __ldg(g_edges + i);
            float4 r1 = __ldg(g_edges + i + 4);
            float4 r2 = __ldg(g_edges + i + 8);
            float4 r3 = __ldg(g_edges + i + 12);
            uint4 u0 = __ldg((const uint4*)(hin_b + (size_t)__float_as_int(r0.x) * D) + f8);
            uint4 u1 = __ldg((const uint4*)(hin_b + (size_t)__float_as_int(r1.x) * D) + f8);
            uint4 u2 = __ldg((const uint4*)(hin_b + (size_t)__float_as_int(r2.x) * D) + f8);
            uint4 u3 = __ldg((const uint4*)(hin_b + (size_t)__float_as_int(r3.x) * D) + f8);
            float w0 = (L == 0) ? r0.y : (L == 1) ? r0.z : r0.w;
            float w1 = (L == 0) ? r1.y : (L == 1) ? r1.z : r1.w;
            float w2 = (L == 0) ? r2.y : (L == 1) ? r2.z : r2.w;
            float w3 = (L == 0) ? r3.y : (L == 1) ? r3.z : r3.w;
            cvt_fma8(acc,  u0, w0); cw  += w0;
            cvt_fma8(acc2, u1, w1); cw2 += w1;
            cvt_fma8(acc,  u2, w2); cw  += w2;
            cvt_fma8(acc2, u3, w3); cw2 += w3;
        }
        for (; i < end; i += 4) {
            float4 re = __ldg(g_edges + i);
            float we = (L == 0) ? re.y : (L == 1) ? re.z : re.w;
            uint4 u = __ldg((const uint4*)(hin_b + (size_t)__float_as_int(re.x) * D) + f8);
            cvt_fma8(acc, u, we); cw += we;
        }
#pragma unroll
        for (int j = 0; j < 8; j++) acc[j] += acc2[j];
        cw += cw2;

        // reduce over the 4 quarters (lane bits 3,4)
#pragma unroll
        for (int j = 0; j < 8; j++) {
            acc[j] += __shfl_xor_sync(0xffffffffu, acc[j], 8);
            acc[j] += __shfl_xor_sync(0xffffffffu, acc[j], 16);
        }
        // c = sum w; each edge's w counted by its 8 lanes -> exact /8
#pragma unroll
        for (int o = 16; o > 0; o >>= 1)
            cw += __shfl_xor_sync(0xffffffffu, cw, o);
        cw *= (1.f / 8.f);

        if (lane < 8) {
#pragma unroll
            for (int j = 0; j < 8; j++)
                sA[warp][f8 * 8 + j] = acc[j];
        }
        __syncwarp();

        float hi0 = hin[(size_t)r * D + lane];
        float hi1 = hin[(size_t)r * D + lane + 32];

        float a0 = sA[warp][lane]      - cw * hi0;
        float a1 = sA[warp][lane + 32] - cw * hi1;
        __syncwarp();

        float acc0 = 0.f, acc1 = 0.f;
#pragma unroll
        for (int k = 0; k < 32; k++) {
            float ak = __shfl_sync(0xffffffffu, a0, k);
            acc0 = fmaf(ak, sW[lane][k], acc0);
            acc1 = fmaf(ak, sW[lane + 32][k], acc1);
        }
#pragma unroll
        for (int k = 0; k < 32; k++) {
            float ak = __shfl_sync(0xffffffffu, a1, k);
            acc0 = fmaf(ak, sW[lane][k + 32], acc0);
            acc1 = fmaf(ak, sW[lane + 32][k + 32], acc1);
        }

        float h0 = fmaxf(acc0 + sb[lane], 0.f);
        float h1 = fmaxf(acc1 + sb[lane + 32], 0.f);

        float s2 = h0 + h1;
        float sq = h0 * h0 + h1 * h1;
#pragma unroll
        for (int o = 16; o > 0; o >>= 1) {
            s2 += __shfl_xor_sync(0xffffffffu, s2, o);
            sq += __shfl_xor_sync(0xffffffffu, sq, o);
        }
        float mu  = s2 * (1.f / D);
        float var = sq * (1.f / D) - mu * mu;
        float inv = rsqrtf(var + 1e-5f);

        float o0 = (h0 - mu) * inv * sg[lane]      + sbt[lane]      + hi0;
        float o1 = (h1 - mu) * inv * sg[lane + 32] + sbt[lane + 32] + hi1;

        if (FUSE_FC) {
            float f0 = 0.f, f1 = 0.f;
#pragma unroll
            for (int k = 0; k < 32; k++) {
                float hk = __shfl_sync(0xffffffffu, o0, k);
                f0 = fmaf(hk, sF[lane][k], f0);
                f1 = fmaf(hk, sF[lane + 32][k], f1);
            }
#pragma unroll
            for (int k = 0; k < 32; k++) {
                float hk = __shfl_sync(0xffffffffu, o1, k);
                f0 = fmaf(hk, sF[lane][k + 32], f0);
                f1 = fmaf(hk, sF[lane + 32][k + 32], f1);
            }
            hout[(size_t)r * D + lane]      = f0 + sfb[lane];
            hout[(size_t)r * D + lane + 32] = f1 + sfb[lane + 32];
        } else {
            hout[(size_t)r * D + lane]      = o0;
            hout[(size_t)r * D + lane + 32] = o1;
            hout_b[(size_t)r * D + lane]      = __float2bfloat16(o0);
            hout_b[(size_t)r * D + lane + 32] = __float2bfloat16(o1);
        }
    }
}

// ---------------------------------------------------------------------------
extern "C" void kernel_launch(void* const* d_in, const int* in_sizes, int n_in,
                              void* d_out, int out_size)
{
    const float* x      = (const float*)d_in[0];
    const void*  eidx   = d_in[1];
    const float* eattr  = (const float*)d_in[2];
    const float* lin_w  = (const float*)d_in[3];
    const float* lin_b  = (const float*)d_in[4];
    const float* emlp_w = (const float*)d_in[5];
    const float* emlp_b = (const float*)d_in[6];
    const float* gamma  = (const float*)d_in[7];
    const float* beta   = (const float*)d_in[8];
    const float* fc_w   = (const float*)d_in[9];
    const float* fc_b   = (const float*)d_in[10];
    float*       out    = (float*)d_out;

    const int E = in_sizes[1] / 2;
    const int N = in_sizes[0] / D;

    float *hA, *hB;
    __nv_bfloat16 *xb, *hbA, *hbB;
    cudaGetSymbolAddress((void**)&hA,  g_hA);
    cudaGetSymbolAddress((void**)&hB,  g_hB);
    cudaGetSymbolAddress((void**)&xb,  g_xb);
    cudaGetSymbolAddress((void**)&hbA, g_hbA);
    cudaGetSymbolAddress((void**)&hbB, g_hbB);

    // --- build: 5 launches ---
    const int NB = (N + SCAN_B - 1) / SCAN_B;
    init_kernel<<<(N + 255) / 256, 256>>>((const int*)eidx, N, NB);
    hist_kernel<<<(E + 255) / 256, 256>>>(eidx, E);
    scan_lookback<<<NB, SCAN_B>>>(N);
    place_kernel<<<(E + 255) / 256, 256>>>(eidx, eattr, emlp_w, emlp_b, E);
    f2bf_kernel<<<(N * D / 4 + 255) / 256, 256>>>(x, xb, N * D);

    // --- layers (fused gather + GEMM + LN + residual) ---
    const int blocks = 2960, threads = 256;

    layer_kernel<0, false><<<blocks, threads>>>(x,  xb,  hA, hbA,
                                                lin_w, lin_b, gamma, beta,
                                                nullptr, nullptr, N);
    layer_kernel<1, false><<<blocks, threads>>>(hA, hbA, hB, hbB,
                                                lin_w + (size_t)D * D, lin_b + D,
                                                gamma + D, beta + D,
                                                nullptr, nullptr, N);
    layer_kernel<2, true><<<blocks, threads>>>(hB, hbB, out, nullptr,
                                               lin_w + (size_t)2 * D * D, lin_b + 2 * D,
                                               gamma + 2 * D, beta + 2 * D,
                                               fc_w, fc_b, N);
}

// round 13
// speedup vs baseline: 1.0628x; 1.0285x over previous
#include <cuda_runtime.h>
#include <cuda_bf16.h>
#include <math.h>

#define N_NODES_MAX 100000
#define N_EDGES_MAX 3200000
#define D 64
#define NL 3
#define SCAN_B 256
#define MAX_NB ((N_NODES_MAX + SCAN_B - 1) / SCAN_B + 1)

// ---- device scratch (no allocation allowed). 256B-aligned for vector loads. ----
__device__ __align__(256) float4 g_edges[N_EDGES_MAX];   // {src, w_l0, w_l1, w_l2}
__device__ __align__(256) int   g_deg[N_NODES_MAX];
__device__ __align__(256) int   g_offs[N_NODES_MAX + 1];
__device__ __align__(256) int   g_cur[N_NODES_MAX];
__device__ __align__(256) int   g_bsum[MAX_NB];
__device__ __align__(256) int   g_boff[MAX_NB];
__device__ __align__(256) float g_hA[(size_t)N_NODES_MAX * D];
__device__ __align__(256) float g_hB[(size_t)N_NODES_MAX * D];
__device__ __align__(256) __nv_bfloat16 g_xb [(size_t)N_NODES_MAX * D];
__device__ __align__(256) __nv_bfloat16 g_hbA[(size_t)N_NODES_MAX * D];
__device__ __align__(256) __nv_bfloat16 g_hbB[(size_t)N_NODES_MAX * D];
__device__ int g_is64;

// ---------------------------------------------------------------------------
// Kernel 1: init — zero deg; convert x -> bf16 shadow; block 0 probes
// edge_index dtype (int64 LE node ids < 2^31 => every odd 32-bit word is 0).
// Grid sized for the bf16 conversion (the larger job).
// ---------------------------------------------------------------------------
__global__ void init_kernel(const int* __restrict__ w32,
                            const float* __restrict__ x,
                            __nv_bfloat16* __restrict__ xb,
                            int N, int nfeat)
{
    int i = blockIdx.x * blockDim.x + threadIdx.x;
    if (i < N) g_deg[i] = 0;

    int idx = i * 4;
    if (idx < nfeat) {
        float4 v = *(const float4*)(x + idx);
        *(__nv_bfloat162*)(xb + idx)     = __floats2bfloat162_rn(v.x, v.y);
        *(__nv_bfloat162*)(xb + idx + 2) = __floats2bfloat162_rn(v.z, v.w);
    }

    if (blockIdx.x == 0) {
        __shared__ int any;
        if (threadIdx.x == 0) any = 0;
        __syncthreads();
        int acc = 0;
        for (int k = threadIdx.x * 2 + 1; k < 4096; k += blockDim.x * 2)
            acc |= w32[k];
        if (acc) atomicOr(&any, 1);
        __syncthreads();
        if (threadIdx.x == 0) g_is64 = (any == 0) ? 1 : 0;
    }
}

// ---------------------------------------------------------------------------
// Kernel 2: in-degree histogram over dst.
// ---------------------------------------------------------------------------
__global__ void hist_kernel(const void* __restrict__ eidx_raw, int E)
{
    int e = blockIdx.x * blockDim.x + threadIdx.x;
    if (e >= E) return;
    int d;
    if (g_is64) d = (int)((const long long*)eidx_raw)[(size_t)E + e];
    else        d = ((const int*)eidx_raw)[(size_t)E + e];
    atomicAdd(&g_deg[d], 1);
}

// ---------------------------------------------------------------------------
// Kernel 3a/3b/3c: 3-phase exclusive scan (measured-fast in R6-R9).
// ---------------------------------------------------------------------------
__global__ void scan_phase1(int N)
{
    __shared__ int sh[SCAN_B];
    const int tid = threadIdx.x;
    const int i = blockIdx.x * SCAN_B + tid;
    int v = (i < N) ? g_deg[i] : 0;
    sh[tid] = v;
    __syncthreads();
    for (int off = 1; off < SCAN_B; off <<= 1) {
        int a = sh[tid];
        int b = (tid >= off) ? sh[tid - off] : 0;
        __syncthreads();
        sh[tid] = a + b;
        __syncthreads();
    }
    if (i < N) g_offs[i] = sh[tid] - v;
    if (tid == SCAN_B - 1) g_bsum[blockIdx.x] = sh[SCAN_B - 1];
}

__global__ void scan_phase2(int NB)
{
    __shared__ int sh[1024];
    const int tid = threadIdx.x;
    int v = (tid < NB) ? g_bsum[tid] : 0;
    sh[tid] = v;
    __syncthreads();
    for (int off = 1; off < 1024; off <<= 1) {
        int a = sh[tid];
        int b = (tid >= off) ? sh[tid - off] : 0;
        __syncthreads();
        sh[tid] = a + b;
        __syncthreads();
    }
    if (tid < NB) g_boff[tid] = sh[tid] - v;
}

__global__ void scan_phase3(int N)
{
    const int i = blockIdx.x * SCAN_B + threadIdx.x;
    if (i < N) {
        int o = g_offs[i] + g_boff[blockIdx.x];
        g_offs[i] = o;
        g_cur[i]  = o;
        if (i == N - 1) g_offs[N] = o + g_deg[i];
    }
}

// ---------------------------------------------------------------------------
// Kernel 4: edge placement into CSR slots + softplus weights (all 3 layers).
// ---------------------------------------------------------------------------
__global__ void place_kernel(const void* __restrict__ eidx_raw,
                             const float* __restrict__ eattr,
                             const float* __restrict__ emlp_w,
                             const float* __restrict__ emlp_b,
                             int E)
{
    int e = blockIdx.x * blockDim.x + threadIdx.x;
    if (e >= E) return;

    int s, d;
    if (g_is64) {
        const long long* p = (const long long*)eidx_raw;
        s = (int)p[e];
        d = (int)p[(size_t)E + e];
    } else {
        const int* p = (const int*)eidx_raw;
        s = p[e];
        d = p[(size_t)E + e];
    }

    const float4 a0 = *(const float4*)(eattr + (size_t)e * 8);
    const float4 a1 = *(const float4*)(eattr + (size_t)e * 8 + 4);

    float sp[NL];
#pragma unroll
    for (int l = 0; l < NL; l++) {
        const float* wp = emlp_w + l * 8;
        float z = emlp_b[l];
        z = fmaf(a0.x, wp[0], z);
        z = fmaf(a0.y, wp[1], z);
        z = fmaf(a0.z, wp[2], z);
        z = fmaf(a0.w, wp[3], z);
        z = fmaf(a1.x, wp[4], z);
        z = fmaf(a1.y, wp[5], z);
        z = fmaf(a1.z, wp[6], z);
        z = fmaf(a1.w, wp[7], z);
        sp[l] = fmaxf(z, 0.f) + log1pf(expf(-fabsf(z)));
    }

    int pos = atomicAdd(&g_cur[d], 1);
    g_edges[pos] = make_float4(__int_as_float(s), sp[0], sp[1], sp[2]);
}

// ---------------------------------------------------------------------------
__device__ __forceinline__ void cvt_fma8(float* acc, uint4 u, float w)
{
    float2 p;
    p = __bfloat1622float2(*reinterpret_cast<__nv_bfloat162*>(&u.x));
    acc[0] = fmaf(w, p.x, acc[0]); acc[1] = fmaf(w, p.y, acc[1]);
    p = __bfloat1622float2(*reinterpret_cast<__nv_bfloat162*>(&u.y));
    acc[2] = fmaf(w, p.x, acc[2]); acc[3] = fmaf(w, p.y, acc[3]);
    p = __bfloat1622float2(*reinterpret_cast<__nv_bfloat162*>(&u.z));
    acc[4] = fmaf(w, p.x, acc[4]); acc[5] = fmaf(w, p.y, acc[5]);
    p = __bfloat1622float2(*reinterpret_cast<__nv_bfloat162*>(&u.w));
    acc[6] = fmaf(w, p.x, acc[6]); acc[7] = fmaf(w, p.y, acc[7]);
}

// ---------------------------------------------------------------------------
// Fused per-layer kernel (R9 structure) + forced 3 CTAs/SM for latency cover.
// Warp per node r. Gather: 16 edges/warp-pass (MLP=4 per 8-lane quarter).
// Epilogue GEMM: shuffle-broadcast a, smem weights (+1 pad), 2 outputs/lane.
// ---------------------------------------------------------------------------
template <int L, bool FUSE_FC>
__global__ void __launch_bounds__(256, 3)
layer_kernel(const float* __restrict__ hin,
             const __nv_bfloat16* __restrict__ hin_b,
             float* __restrict__ hout,
             __nv_bfloat16* __restrict__ hout_b,   // may be null
             const float* __restrict__ W,
             const float* __restrict__ bias,
             const float* __restrict__ gamma,
             const float* __restrict__ beta,
             const float* __restrict__ fcW,
             const float* __restrict__ fcb,
             int N)
{
    __shared__ float sW[D][D + 1];
    __shared__ float sF[FUSE_FC ? D : 1][FUSE_FC ? (D + 1) : 1];
    __shared__ float sb[D], sg[D], sbt[D], sfb[D];
    __shared__ float sA[8][D];   // 8 warps per block

    for (int i = threadIdx.x; i < D * D; i += blockDim.x) {
        sW[i >> 6][i & 63] = W[i];
        if (FUSE_FC) sF[i >> 6][i & 63] = fcW[i];
    }
    if (threadIdx.x < D) {
        sb[threadIdx.x]  = bias[threadIdx.x];
        sg[threadIdx.x]  = gamma[threadIdx.x];
        sbt[threadIdx.x] = beta[threadIdx.x];
        if (FUSE_FC) sfb[threadIdx.x] = fcb[threadIdx.x];
    }
    __syncthreads();

    const int warp = threadIdx.x >> 5;
    const int lane = threadIdx.x & 31;
    const int f8      = lane & 7;    // which 16B (8-bf16) chunk of the 128B row
    const int quarter = lane >> 3;   // which of 4 concurrent edges
    const int warps_per_grid = (blockDim.x >> 5) * gridDim.x;

    for (int r = blockIdx.x * (blockDim.x >> 5) + warp; r < N; r += warps_per_grid) {
        const int start = __ldg(g_offs + r);
        const int end   = __ldg(g_offs + r + 1);

        float acc [8] = {0.f, 0.f, 0.f, 0.f, 0.f, 0.f, 0.f, 0.f};
        float acc2[8] = {0.f, 0.f, 0.f, 0.f, 0.f, 0.f, 0.f, 0.f};
        float cw = 0.f, cw2 = 0.f;

        int i = start + quarter;
        // 4 edges in flight per quarter (16 per warp pass)
        for (; i + 12 < end; i += 16) {
            float4 r0 = __ldg(g_edges + i);
            float4 r1 = __ldg(g_edges + i + 4);
            float4 r2 = __ldg(g_edges + i + 8);
            float4 r3 = __ldg(g_edges + i + 12);
            uint4 u0 = __ldg((const uint4*)(hin_b + (size_t)__float_as_int(r0.x) * D) + f8);
            uint4 u1 = __ldg((const uint4*)(hin_b + (size_t)__float_as_int(r1.x) * D) + f8);
            uint4 u2 = __ldg((const uint4*)(hin_b + (size_t)__float_as_int(r2.x) * D) + f8);
            uint4 u3 = __ldg((const uint4*)(hin_b + (size_t)__float_as_int(r3.x) * D) + f8);
            float w0 = (L == 0) ? r0.y : (L == 1) ? r0.z : r0.w;
            float w1 = (L == 0) ? r1.y : (L == 1) ? r1.z : r1.w;
            float w2 = (L == 0) ? r2.y : (L == 1) ? r2.z : r2.w;
            float w3 = (L == 0) ? r3.y : (L == 1) ? r3.z : r3.w;
            cvt_fma8(acc,  u0, w0); cw  += w0;
            cvt_fma8(acc2, u1, w1); cw2 += w1;
            cvt_fma8(acc,  u2, w2); cw  += w2;
            cvt_fma8(acc2, u3, w3); cw2 += w3;
        }
        for (; i < end; i += 4) {
            float4 re = __ldg(g_edges + i);
            float we = (L == 0) ? re.y : (L == 1) ? re.z : re.w;
            uint4 u = __ldg((const uint4*)(hin_b + (size_t)__float_as_int(re.x) * D) + f8);
            cvt_fma8(acc, u, we); cw += we;
        }
#pragma unroll
        for (int j = 0; j < 8; j++) acc[j] += acc2[j];
        cw += cw2;

        // reduce over the 4 quarters (lane bits 3,4)
#pragma unroll
        for (int j = 0; j < 8; j++) {
            acc[j] += __shfl_xor_sync(0xffffffffu, acc[j], 8);
            acc[j] += __shfl_xor_sync(0xffffffffu, acc[j], 16);
        }
        // c = sum w; each edge's w counted by its 8 lanes -> exact /8
#pragma unroll
        for (int o = 16; o > 0; o >>= 1)
            cw += __shfl_xor_sync(0xffffffffu, cw, o);
        cw *= (1.f / 8.f);

        if (lane < 8) {
#pragma unroll
            for (int j = 0; j < 8; j++)
                sA[warp][f8 * 8 + j] = acc[j];
        }
        __syncwarp();

        float hi0 = hin[(size_t)r * D + lane];
        float hi1 = hin[(size_t)r * D + lane + 32];

        float a0 = sA[warp][lane]      - cw * hi0;
        float a1 = sA[warp][lane + 32] - cw * hi1;
        __syncwarp();

        float acc0 = 0.f, acc1 = 0.f;
#pragma unroll
        for (int k = 0; k < 32; k++) {
            float ak = __shfl_sync(0xffffffffu, a0, k);
            acc0 = fmaf(ak, sW[lane][k], acc0);
            acc1 = fmaf(ak, sW[lane + 32][k], acc1);
        }
#pragma unroll
        for (int k = 0; k < 32; k++) {
            float ak = __shfl_sync(0xffffffffu, a1, k);
            acc0 = fmaf(ak, sW[lane][k + 32], acc0);
            acc1 = fmaf(ak, sW[lane + 32][k + 32], acc1);
        }

        float h0 = fmaxf(acc0 + sb[lane], 0.f);
        float h1 = fmaxf(acc1 + sb[lane + 32], 0.f);

        float s2 = h0 + h1;
        float sq = h0 * h0 + h1 * h1;
#pragma unroll
        for (int o = 16; o > 0; o >>= 1) {
            s2 += __shfl_xor_sync(0xffffffffu, s2, o);
            sq += __shfl_xor_sync(0xffffffffu, sq, o);
        }
        float mu  = s2 * (1.f / D);
        float var = sq * (1.f / D) - mu * mu;
        float inv = rsqrtf(var + 1e-5f);

        float o0 = (h0 - mu) * inv * sg[lane]      + sbt[lane]      + hi0;
        float o1 = (h1 - mu) * inv * sg[lane + 32] + sbt[lane + 32] + hi1;

        if (FUSE_FC) {
            float f0 = 0.f, f1 = 0.f;
#pragma unroll
            for (int k = 0; k < 32; k++) {
                float hk = __shfl_sync(0xffffffffu, o0, k);
                f0 = fmaf(hk, sF[lane][k], f0);
                f1 = fmaf(hk, sF[lane + 32][k], f1);
            }
#pragma unroll
            for (int k = 0; k < 32; k++) {
                float hk = __shfl_sync(0xffffffffu, o1, k);
                f0 = fmaf(hk, sF[lane][k + 32], f0);
                f1 = fmaf(hk, sF[lane + 32][k + 32], f1);
            }
            hout[(size_t)r * D + lane]      = f0 + sfb[lane];
            hout[(size_t)r * D + lane + 32] = f1 + sfb[lane + 32];
        } else {
            hout[(size_t)r * D + lane]      = o0;
            hout[(size_t)r * D + lane + 32] = o1;
            hout_b[(size_t)r * D + lane]      = __float2bfloat16(o0);
            hout_b[(size_t)r * D + lane + 32] = __float2bfloat16(o1);
        }
    }
}

// ---------------------------------------------------------------------------
extern "C" void kernel_launch(void* const* d_in, const int* in_sizes, int n_in,
                              void* d_out, int out_size)
{
    const float* x      = (const float*)d_in[0];
    const void*  eidx   = d_in[1];
    const float* eattr  = (const float*)d_in[2];
    const float* lin_w  = (const float*)d_in[3];
    const float* lin_b  = (const float*)d_in[4];
    const float* emlp_w = (const float*)d_in[5];
    const float* emlp_b = (const float*)d_in[6];
    const float* gamma  = (const float*)d_in[7];
    const float* beta   = (const float*)d_in[8];
    const float* fc_w   = (const float*)d_in[9];
    const float* fc_b   = (const float*)d_in[10];
    float*       out    = (float*)d_out;

    const int E = in_sizes[1] / 2;
    const int N = in_sizes[0] / D;

    float *hA, *hB;
    __nv_bfloat16 *xb, *hbA, *hbB;
    cudaGetSymbolAddress((void**)&hA,  g_hA);
    cudaGetSymbolAddress((void**)&hB,  g_hB);
    cudaGetSymbolAddress((void**)&xb,  g_xb);
    cudaGetSymbolAddress((void**)&hbA, g_hbA);
    cudaGetSymbolAddress((void**)&hbB, g_hbB);

    // --- build: 6 launches (init merges deg-zero + dtype probe + f2bf) ---
    const int NB = (N + SCAN_B - 1) / SCAN_B;
    const int nfeat = N * D;
    const int init_blocks = (nfeat / 4 + 255) / 256;   // covers N too (nfeat/4 >= N)
    init_kernel<<<init_blocks, 256>>>((const int*)eidx, x, xb, N, nfeat);
    hist_kernel<<<(E + 255) / 256, 256>>>(eidx, E);
    scan_phase1<<<NB, SCAN_B>>>(N);
    scan_phase2<<<1, 1024>>>(NB);
    scan_phase3<<<NB, SCAN_B>>>(N);
    place_kernel<<<(E + 255) / 256, 256>>>(eidx, eattr, emlp_w, emlp_b, E);

    // --- layers (fused gather + GEMM + LN + residual) ---
    const int blocks = 2960, threads = 256;

    layer_kernel<0, false><<<blocks, threads>>>(x,  xb,  hA, hbA,
                                                lin_w, lin_b, gamma, beta,
                                                nullptr, nullptr, N);
    layer_kernel<1, false><<<blocks, threads>>>(hA, hbA, hB, hbB,
                                                lin_w + (size_t)D * D, lin_b + D,
                                                gamma + D, beta + D,
                                                nullptr, nullptr, N);
    layer_kernel<2, true><<<blocks, threads>>>(hB, hbB, out, nullptr,
                                               lin_w + (size_t)2 * D * D, lin_b + 2 * D,
                                               gamma + 2 * D, beta + 2 * D,
                                               fc_w, fc_b, N);
}

// round 14
// speedup vs baseline: 1.1261x; 1.0596x over previous
#include <cuda_runtime.h>
#include <cuda_bf16.h>
#include <math.h>

#define N_NODES_MAX 100000
#define N_EDGES_MAX 3200000
#define D 64
#define NL 3
#define SCAN_B 256
#define MAX_NB ((N_NODES_MAX + SCAN_B - 1) / SCAN_B + 1)

// ---- device scratch (no allocation allowed). 256B-aligned for vector loads. ----
__device__ __align__(256) float4 g_edges[N_EDGES_MAX];   // {src, w_l0, w_l1, w_l2}
__device__ __align__(256) int   g_deg[N_NODES_MAX];
__device__ __align__(256) int   g_offs[N_NODES_MAX + 1];
__device__ __align__(256) int   g_cur[N_NODES_MAX];
__device__ __align__(256) int   g_bsum[MAX_NB];
__device__ __align__(256) int   g_boff[MAX_NB];
__device__ __align__(256) float g_ga[(size_t)N_NODES_MAX * D];   // corrected activations
__device__ __align__(256) float g_hA[(size_t)N_NODES_MAX * D];
__device__ __align__(256) float g_hB[(size_t)N_NODES_MAX * D];
__device__ __align__(256) __nv_bfloat16 g_xb [(size_t)N_NODES_MAX * D];
__device__ __align__(256) __nv_bfloat16 g_hbA[(size_t)N_NODES_MAX * D];
__device__ __align__(256) __nv_bfloat16 g_hbB[(size_t)N_NODES_MAX * D];
__device__ int g_is64;

// ---------------------------------------------------------------------------
// Kernel 1: init — zero deg; convert x -> bf16 shadow; block 0 probes dtype.
// ---------------------------------------------------------------------------
__global__ void init_kernel(const int* __restrict__ w32,
                            const float* __restrict__ x,
                            __nv_bfloat16* __restrict__ xb,
                            int N, int nfeat)
{
    int i = blockIdx.x * blockDim.x + threadIdx.x;
    if (i < N) g_deg[i] = 0;

    int idx = i * 4;
    if (idx < nfeat) {
        float4 v = *(const float4*)(x + idx);
        *(__nv_bfloat162*)(xb + idx)     = __floats2bfloat162_rn(v.x, v.y);
        *(__nv_bfloat162*)(xb + idx + 2) = __floats2bfloat162_rn(v.z, v.w);
    }

    if (blockIdx.x == 0) {
        __shared__ int any;
        if (threadIdx.x == 0) any = 0;
        __syncthreads();
        int acc = 0;
        for (int k = threadIdx.x * 2 + 1; k < 4096; k += blockDim.x * 2)
            acc |= w32[k];
        if (acc) atomicOr(&any, 1);
        __syncthreads();
        if (threadIdx.x == 0) g_is64 = (any == 0) ? 1 : 0;
    }
}

// ---------------------------------------------------------------------------
__global__ void hist_kernel(const void* __restrict__ eidx_raw, int E)
{
    int e = blockIdx.x * blockDim.x + threadIdx.x;
    if (e >= E) return;
    int d;
    if (g_is64) d = (int)((const long long*)eidx_raw)[(size_t)E + e];
    else        d = ((const int*)eidx_raw)[(size_t)E + e];
    atomicAdd(&g_deg[d], 1);
}

// ---------------------------------------------------------------------------
__global__ void scan_phase1(int N)
{
    __shared__ int sh[SCAN_B];
    const int tid = threadIdx.x;
    const int i = blockIdx.x * SCAN_B + tid;
    int v = (i < N) ? g_deg[i] : 0;
    sh[tid] = v;
    __syncthreads();
    for (int off = 1; off < SCAN_B; off <<= 1) {
        int a = sh[tid];
        int b = (tid >= off) ? sh[tid - off] : 0;
        __syncthreads();
        sh[tid] = a + b;
        __syncthreads();
    }
    if (i < N) g_offs[i] = sh[tid] - v;
    if (tid == SCAN_B - 1) g_bsum[blockIdx.x] = sh[SCAN_B - 1];
}

__global__ void scan_phase2(int NB)
{
    __shared__ int sh[1024];
    const int tid = threadIdx.x;
    int v = (tid < NB) ? g_bsum[tid] : 0;
    sh[tid] = v;
    __syncthreads();
    for (int off = 1; off < 1024; off <<= 1) {
        int a = sh[tid];
        int b = (tid >= off) ? sh[tid - off] : 0;
        __syncthreads();
        sh[tid] = a + b;
        __syncthreads();
    }
    if (tid < NB) g_boff[tid] = sh[tid] - v;
}

__global__ void scan_phase3(int N)
{
    const int i = blockIdx.x * SCAN_B + threadIdx.x;
    if (i < N) {
        int o = g_offs[i] + g_boff[blockIdx.x];
        g_offs[i] = o;
        g_cur[i]  = o;
        if (i == N - 1) g_offs[N] = o + g_deg[i];
    }
}

// ---------------------------------------------------------------------------
__global__ void place_kernel(const void* __restrict__ eidx_raw,
                             const float* __restrict__ eattr,
                             const float* __restrict__ emlp_w,
                             const float* __restrict__ emlp_b,
                             int E)
{
    int e = blockIdx.x * blockDim.x + threadIdx.x;
    if (e >= E) return;

    int s, d;
    if (g_is64) {
        const long long* p = (const long long*)eidx_raw;
        s = (int)p[e];
        d = (int)p[(size_t)E + e];
    } else {
        const int* p = (const int*)eidx_raw;
        s = p[e];
        d = p[(size_t)E + e];
    }

    const float4 a0 = *(const float4*)(eattr + (size_t)e * 8);
    const float4 a1 = *(const float4*)(eattr + (size_t)e * 8 + 4);

    float sp[NL];
#pragma unroll
    for (int l = 0; l < NL; l++) {
        const float* wp = emlp_w + l * 8;
        float z = emlp_b[l];
        z = fmaf(a0.x, wp[0], z);
        z = fmaf(a0.y, wp[1], z);
        z = fmaf(a0.z, wp[2], z);
        z = fmaf(a0.w, wp[3], z);
        z = fmaf(a1.x, wp[4], z);
        z = fmaf(a1.y, wp[5], z);
        z = fmaf(a1.z, wp[6], z);
        z = fmaf(a1.w, wp[7], z);
        sp[l] = fmaxf(z, 0.f) + log1pf(expf(-fabsf(z)));
    }

    int pos = atomicAdd(&g_cur[d], 1);
    g_edges[pos] = make_float4(__int_as_float(s), sp[0], sp[1], sp[2]);
}

// ---------------------------------------------------------------------------
__device__ __forceinline__ void cvt_fma8(float* acc, uint4 u, float w)
{
    float2 p;
    p = __bfloat1622float2(*reinterpret_cast<__nv_bfloat162*>(&u.x));
    acc[0] = fmaf(w, p.x, acc[0]); acc[1] = fmaf(w, p.y, acc[1]);
    p = __bfloat1622float2(*reinterpret_cast<__nv_bfloat162*>(&u.y));
    acc[2] = fmaf(w, p.x, acc[2]); acc[3] = fmaf(w, p.y, acc[3]);
    p = __bfloat1622float2(*reinterpret_cast<__nv_bfloat162*>(&u.z));
    acc[4] = fmaf(w, p.x, acc[4]); acc[5] = fmaf(w, p.y, acc[5]);
    p = __bfloat1622float2(*reinterpret_cast<__nv_bfloat162*>(&u.w));
    acc[6] = fmaf(w, p.x, acc[6]); acc[7] = fmaf(w, p.y, acc[7]);
}

// ---------------------------------------------------------------------------
// Gather kernel. Warp per node r; 16 edges/warp-pass (MLP=4 per quarter).
// Writes corrected activation a = sum w*h_b[src] - (sum w)*h[r] to ga.
// ---------------------------------------------------------------------------
template <int L>
__global__ void __launch_bounds__(256)
gather_kernel(const float* __restrict__ hin,
              const __nv_bfloat16* __restrict__ hin_b,
              float* __restrict__ ga, int N)
{
    const int warp = threadIdx.x >> 5;
    const int lane = threadIdx.x & 31;
    const int f8      = lane & 7;
    const int quarter = lane >> 3;
    const int warps_per_grid = (blockDim.x >> 5) * gridDim.x;

    for (int r = blockIdx.x * (blockDim.x >> 5) + warp; r < N; r += warps_per_grid) {
        const int start = __ldg(g_offs + r);
        const int end   = __ldg(g_offs + r + 1);

        float acc [8] = {0.f, 0.f, 0.f, 0.f, 0.f, 0.f, 0.f, 0.f};
        float acc2[8] = {0.f, 0.f, 0.f, 0.f, 0.f, 0.f, 0.f, 0.f};
        float cw = 0.f, cw2 = 0.f;

        int i = start + quarter;
        for (; i + 12 < end; i += 16) {
            float4 r0 = __ldg(g_edges + i);
            float4 r1 = __ldg(g_edges + i + 4);
            float4 r2 = __ldg(g_edges + i + 8);
            float4 r3 = __ldg(g_edges + i + 12);
            uint4 u0 = __ldg((const uint4*)(hin_b + (size_t)__float_as_int(r0.x) * D) + f8);
            uint4 u1 = __ldg((const uint4*)(hin_b + (size_t)__float_as_int(r1.x) * D) + f8);
            uint4 u2 = __ldg((const uint4*)(hin_b + (size_t)__float_as_int(r2.x) * D) + f8);
            uint4 u3 = __ldg((const uint4*)(hin_b + (size_t)__float_as_int(r3.x) * D) + f8);
            float w0 = (L == 0) ? r0.y : (L == 1) ? r0.z : r0.w;
            float w1 = (L == 0) ? r1.y : (L == 1) ? r1.z : r1.w;
            float w2 = (L == 0) ? r2.y : (L == 1) ? r2.z : r2.w;
            float w3 = (L == 0) ? r3.y : (L == 1) ? r3.z : r3.w;
            cvt_fma8(acc,  u0, w0); cw  += w0;
            cvt_fma8(acc2, u1, w1); cw2 += w1;
            cvt_fma8(acc,  u2, w2); cw  += w2;
            cvt_fma8(acc2, u3, w3); cw2 += w3;
        }
        for (; i < end; i += 4) {
            float4 re = __ldg(g_edges + i);
            float we = (L == 0) ? re.y : (L == 1) ? re.z : re.w;
            uint4 u = __ldg((const uint4*)(hin_b + (size_t)__float_as_int(re.x) * D) + f8);
            cvt_fma8(acc, u, we); cw += we;
        }
#pragma unroll
        for (int j = 0; j < 8; j++) acc[j] += acc2[j];
        cw += cw2;

#pragma unroll
        for (int j = 0; j < 8; j++) {
            acc[j] += __shfl_xor_sync(0xffffffffu, acc[j], 8);
            acc[j] += __shfl_xor_sync(0xffffffffu, acc[j], 16);
        }
#pragma unroll
        for (int o = 16; o > 0; o >>= 1)
            cw += __shfl_xor_sync(0xffffffffu, cw, o);
        cw *= (1.f / 8.f);

        if (lane < 8) {
            const float* hr = hin + (size_t)r * D + f8 * 8;
            float4 h0 = *(const float4*)hr;
            float4 h1 = *(const float4*)(hr + 4);
            float4 o0 = make_float4(acc[0] - cw * h0.x, acc[1] - cw * h0.y,
                                    acc[2] - cw * h0.z, acc[3] - cw * h0.w);
            float4 o1 = make_float4(acc[4] - cw * h1.x, acc[5] - cw * h1.y,
                                    acc[6] - cw * h1.z, acc[7] - cw * h1.w);
            float* gp = ga + (size_t)r * D + f8 * 8;
            *(float4*)gp       = o0;
            *(float4*)(gp + 4) = o1;
        }
    }
}

// ---------------------------------------------------------------------------
// Node-update kernel: register-tiled GEMM over 64-node tiles.
// 256 threads: thread (tn = tid&15, tc = tid>>4) computes 4 nodes x 4 cols.
//   h  = relu(a @ W^T + b);  o = LN(h)*gamma + beta + hin   [+ FC GEMM]
// ---------------------------------------------------------------------------
template <bool FUSE_FC>
__global__ void __launch_bounds__(256)
nodeupdate_kernel(const float* __restrict__ ga,
                  const float* __restrict__ hin,
                  float* __restrict__ hout,
                  __nv_bfloat16* __restrict__ hout_b,   // null if FUSE_FC
                  const float* __restrict__ W,
                  const float* __restrict__ bias,
                  const float* __restrict__ gamma,
                  const float* __restrict__ beta,
                  const float* __restrict__ fcW,
                  const float* __restrict__ fcb,
                  int N)
{
    __shared__ float sAT[D][72];    // a transposed: sAT[k][node_local]
    __shared__ float sWT[D][68];    // W transposed: sWT[k][col] = W[col][k]
    __shared__ float sred[D][34];   // LN partials: [node][tc] = s, [node][17+tc] = sq
    __shared__ float smu[D], sinv[D];
    __shared__ float sb[D], sg[D], sbt[D], sfb[D];

    const int tid = threadIdx.x;

    for (int i = tid; i < D * D; i += 256) {
        int row = i >> 6, k = i & 63;
        sWT[k][row] = W[i];
    }
    if (tid < D) {
        sb[tid]  = bias[tid];
        sg[tid]  = gamma[tid];
        sbt[tid] = beta[tid];
        if (FUSE_FC) sfb[tid] = fcb[tid];
    }

    const int base = blockIdx.x * 64;
    {
        int node_l = tid >> 2, kq = tid & 3;
        int node = base + node_l;
#pragma unroll
        for (int q = 0; q < 4; q++) {
            int k0 = kq * 16 + q * 4;
            float4 v = make_float4(0.f, 0.f, 0.f, 0.f);
            if (node < N) v = *(const float4*)(ga + (size_t)node * D + k0);
            sAT[k0][node_l]     = v.x;
            sAT[k0 + 1][node_l] = v.y;
            sAT[k0 + 2][node_l] = v.z;
            sAT[k0 + 3][node_l] = v.w;
        }
    }
    __syncthreads();

    const int tn = tid & 15, tc = tid >> 4;

    float acc[4][4] = {};
#pragma unroll
    for (int k = 0; k < D; k++) {
        float4 a4 = *(const float4*)&sAT[k][tn * 4];
        float4 w4 = *(const float4*)&sWT[k][tc * 4];
        float aa[4] = {a4.x, a4.y, a4.z, a4.w};
        float ww[4] = {w4.x, w4.y, w4.z, w4.w};
#pragma unroll
        for (int ni = 0; ni < 4; ni++)
#pragma unroll
            for (int ci = 0; ci < 4; ci++)
                acc[ni][ci] = fmaf(aa[ni], ww[ci], acc[ni][ci]);
    }

    float h[4][4];
#pragma unroll
    for (int ni = 0; ni < 4; ni++) {
        float s = 0.f, sq = 0.f;
#pragma unroll
        for (int ci = 0; ci < 4; ci++) {
            float v = fmaxf(acc[ni][ci] + sb[tc * 4 + ci], 0.f);
            h[ni][ci] = v;
            s += v;
            sq += v * v;
        }
        sred[tn * 4 + ni][tc]      = s;
        sred[tn * 4 + ni][17 + tc] = sq;
    }
    __syncthreads();

    if (tid < 64) {
        float s = 0.f, sq = 0.f;
#pragma unroll
        for (int j = 0; j < 16; j++) {
            s  += sred[tid][j];
            sq += sred[tid][17 + j];
        }
        float mu  = s * (1.f / D);
        float var = sq * (1.f / D) - mu * mu;
        smu[tid]  = mu;
        sinv[tid] = rsqrtf(var + 1e-5f);
    }
    __syncthreads();

    float o[4][4];
#pragma unroll
    for (int ni = 0; ni < 4; ni++) {
        int node = base + tn * 4 + ni;
        float4 hi = make_float4(0.f, 0.f, 0.f, 0.f);
        if (node < N) hi = *(const float4*)(hin + (size_t)node * D + tc * 4);
        float hiv[4] = {hi.x, hi.y, hi.z, hi.w};
        float mu  = smu[tn * 4 + ni];
        float inv = sinv[tn * 4 + ni];
#pragma unroll
        for (int ci = 0; ci < 4; ci++) {
            int col = tc * 4 + ci;
            o[ni][ci] = (h[ni][ci] - mu) * inv * sg[col] + sbt[col] + hiv[ci];
        }
    }

    if (!FUSE_FC) {
#pragma unroll
        for (int ni = 0; ni < 4; ni++) {
            int node = base + tn * 4 + ni;
            if (node < N) {
                float* hp = hout + (size_t)node * D + tc * 4;
                *(float4*)hp = make_float4(o[ni][0], o[ni][1], o[ni][2], o[ni][3]);
                __nv_bfloat16* bp = hout_b + (size_t)node * D + tc * 4;
                *(__nv_bfloat162*)bp       = __floats2bfloat162_rn(o[ni][0], o[ni][1]);
                *(__nv_bfloat162*)(bp + 2) = __floats2bfloat162_rn(o[ni][2], o[ni][3]);
            }
        }
    } else {
        // first-loop reads of sAT/sWT completed before the sred __syncthreads()
        for (int i = tid; i < D * D; i += 256) {
            int row = i >> 6, k = i & 63;
            sWT[k][row] = fcW[i];
        }
#pragma unroll
        for (int ni = 0; ni < 4; ni++)
#pragma unroll
            for (int ci = 0; ci < 4; ci++)
                sAT[tc * 4 + ci][tn * 4 + ni] = o[ni][ci];
        __syncthreads();

        float f[4][4] = {};
#pragma unroll
        for (int k = 0; k < D; k++) {
            float4 a4 = *(const float4*)&sAT[k][tn * 4];
            float4 w4 = *(const float4*)&sWT[k][tc * 4];
            float aa[4] = {a4.x, a4.y, a4.z, a4.w};
            float ww[4] = {w4.x, w4.y, w4.z, w4.w};
#pragma unroll
            for (int ni = 0; ni < 4; ni++)
#pragma unroll
                for (int ci = 0; ci < 4; ci++)
                    f[ni][ci] = fmaf(aa[ni], ww[ci], f[ni][ci]);
        }
#pragma unroll
        for (int ni = 0; ni < 4; ni++) {
            int node = base + tn * 4 + ni;
            if (node < N) {
                float* hp = hout + (size_t)node * D + tc * 4;
                *(float4*)hp = make_float4(f[ni][0] + sfb[tc * 4 + 0],
                                           f[ni][1] + sfb[tc * 4 + 1],
                                           f[ni][2] + sfb[tc * 4 + 2],
                                           f[ni][3] + sfb[tc * 4 + 3]);
            }
        }
    }
}

// ---------------------------------------------------------------------------
extern "C" void kernel_launch(void* const* d_in, const int* in_sizes, int n_in,
                              void* d_out, int out_size)
{
    const float* x      = (const float*)d_in[0];
    const void*  eidx   = d_in[1];
    const float* eattr  = (const float*)d_in[2];
    const float* lin_w  = (const float*)d_in[3];
    const float* lin_b  = (const float*)d_in[4];
    const float* emlp_w = (const float*)d_in[5];
    const float* emlp_b = (const float*)d_in[6];
    const float* gamma  = (const float*)d_in[7];
    const float* beta   = (const float*)d_in[8];
    const float* fc_w   = (const float*)d_in[9];
    const float* fc_b   = (const float*)d_in[10];
    float*       out    = (float*)d_out;

    const int E = in_sizes[1] / 2;
    const int N = in_sizes[0] / D;

    float *hA, *hB, *ga;
    __nv_bfloat16 *xb, *hbA, *hbB;
    cudaGetSymbolAddress((void**)&hA,  g_hA);
    cudaGetSymbolAddress((void**)&hB,  g_hB);
    cudaGetSymbolAddress((void**)&ga,  g_ga);
    cudaGetSymbolAddress((void**)&xb,  g_xb);
    cudaGetSymbolAddress((void**)&hbA, g_hbA);
    cudaGetSymbolAddress((void**)&hbB, g_hbB);

    // --- build ---
    const int NB = (N + SCAN_B - 1) / SCAN_B;
    const int nfeat = N * D;
    const int init_blocks = (nfeat / 4 + 255) / 256;
    init_kernel<<<init_blocks, 256>>>((const int*)eidx, x, xb, N, nfeat);
    hist_kernel<<<(E + 255) / 256, 256>>>(eidx, E);
    scan_phase1<<<NB, SCAN_B>>>(N);
    scan_phase2<<<1, 1024>>>(NB);
    scan_phase3<<<NB, SCAN_B>>>(N);
    place_kernel<<<(E + 255) / 256, 256>>>(eidx, eattr, emlp_w, emlp_b, E);

    // --- layers: gather -> tiled GEMM/LN/residual ---
    const int gblocks = 2960, gthreads = 256;
    const int tblocks = (N + 63) / 64;

    gather_kernel<0><<<gblocks, gthreads>>>(x, xb, ga, N);
    nodeupdate_kernel<false><<<tblocks, 256>>>(ga, x, hA, hbA,
                                               lin_w, lin_b, gamma, beta,
                                               nullptr, nullptr, N);

    gather_kernel<1><<<gblocks, gthreads>>>(hA, hbA, ga, N);
    nodeupdate_kernel<false><<<tblocks, 256>>>(ga, hA, hB, hbB,
                                               lin_w + (size_t)D * D, lin_b + D,
                                               gamma + D, beta + D,
                                               nullptr, nullptr, N);

    gather_kernel<2><<<gblocks, gthreads>>>(hB, hbB, ga, N);
    nodeupdate_kernel<true><<<tblocks, 256>>>(ga, hB, out, nullptr,
                                              lin_w + (size_t)2 * D * D, lin_b + 2 * D,
                                              gamma + 2 * D, beta + 2 * D,
                                              fc_w, fc_b, N);
}

// round 15
// speedup vs baseline: 1.2017x; 1.0671x over previous
#include <cuda_runtime.h>
#include <cuda_bf16.h>
#include <math.h>

#define N_NODES_MAX 100000
#define N_EDGES_MAX 3200000
#define D 64
#define NL 3
#define SCAN_B 256
#define MAX_NB ((N_NODES_MAX + SCAN_B - 1) / SCAN_B + 1)

// ---- device scratch (no allocation allowed). 256B-aligned for vector loads. ----
__device__ __align__(256) float4 g_edges[N_EDGES_MAX];   // {src, w_l0, w_l1, w_l2}
__device__ __align__(256) int   g_deg[N_NODES_MAX];
__device__ __align__(256) int   g_offs[N_NODES_MAX + 1];
__device__ __align__(256) int   g_cur[N_NODES_MAX];
__device__ __align__(256) int   g_bsum[MAX_NB];
__device__ __align__(256) int   g_boff[MAX_NB];
__device__ __align__(256) float g_ga[(size_t)N_NODES_MAX * D];   // corrected activations
__device__ __align__(256) float g_hA[(size_t)N_NODES_MAX * D];
__device__ __align__(256) float g_hB[(size_t)N_NODES_MAX * D];
__device__ __align__(256) __nv_bfloat16 g_xb [(size_t)N_NODES_MAX * D];
__device__ __align__(256) __nv_bfloat16 g_hbA[(size_t)N_NODES_MAX * D];
__device__ __align__(256) __nv_bfloat16 g_hbB[(size_t)N_NODES_MAX * D];
__device__ int g_is64;

// ---------------------------------------------------------------------------
// Kernel 1: init — zero deg; convert x -> bf16 shadow; block 0 probes dtype.
// ---------------------------------------------------------------------------
__global__ void init_kernel(const int* __restrict__ w32,
                            const float* __restrict__ x,
                            __nv_bfloat16* __restrict__ xb,
                            int N, int nfeat)
{
    int i = blockIdx.x * blockDim.x + threadIdx.x;
    if (i < N) g_deg[i] = 0;

    int idx = i * 4;
    if (idx < nfeat) {
        float4 v = *(const float4*)(x + idx);
        *(__nv_bfloat162*)(xb + idx)     = __floats2bfloat162_rn(v.x, v.y);
        *(__nv_bfloat162*)(xb + idx + 2) = __floats2bfloat162_rn(v.z, v.w);
    }

    if (blockIdx.x == 0) {
        __shared__ int any;
        if (threadIdx.x == 0) any = 0;
        __syncthreads();
        int acc = 0;
        for (int k = threadIdx.x * 2 + 1; k < 4096; k += blockDim.x * 2)
            acc |= w32[k];
        if (acc) atomicOr(&any, 1);
        __syncthreads();
        if (threadIdx.x == 0) g_is64 = (any == 0) ? 1 : 0;
    }
}

// ---------------------------------------------------------------------------
__global__ void hist_kernel(const void* __restrict__ eidx_raw, int E)
{
    int e = blockIdx.x * blockDim.x + threadIdx.x;
    if (e >= E) return;
    int d;
    if (g_is64) d = (int)((const long long*)eidx_raw)[(size_t)E + e];
    else        d = ((const int*)eidx_raw)[(size_t)E + e];
    atomicAdd(&g_deg[d], 1);
}

// ---------------------------------------------------------------------------
__global__ void scan_phase1(int N)
{
    __shared__ int sh[SCAN_B];
    const int tid = threadIdx.x;
    const int i = blockIdx.x * SCAN_B + tid;
    int v = (i < N) ? g_deg[i] : 0;
    sh[tid] = v;
    __syncthreads();
    for (int off = 1; off < SCAN_B; off <<= 1) {
        int a = sh[tid];
        int b = (tid >= off) ? sh[tid - off] : 0;
        __syncthreads();
        sh[tid] = a + b;
        __syncthreads();
    }
    if (i < N) g_offs[i] = sh[tid] - v;
    if (tid == SCAN_B - 1) g_bsum[blockIdx.x] = sh[SCAN_B - 1];
}

__global__ void scan_phase2(int NB)
{
    __shared__ int sh[1024];
    const int tid = threadIdx.x;
    int v = (tid < NB) ? g_bsum[tid] : 0;
    sh[tid] = v;
    __syncthreads();
    for (int off = 1; off < 1024; off <<= 1) {
        int a = sh[tid];
        int b = (tid >= off) ? sh[tid - off] : 0;
        __syncthreads();
        sh[tid] = a + b;
        __syncthreads();
    }
    if (tid < NB) g_boff[tid] = sh[tid] - v;
}

__global__ void scan_phase3(int N)
{
    const int i = blockIdx.x * SCAN_B + threadIdx.x;
    if (i < N) {
        int o = g_offs[i] + g_boff[blockIdx.x];
        g_offs[i] = o;
        g_cur[i]  = o;
        if (i == N - 1) g_offs[N] = o + g_deg[i];
    }
}

// ---------------------------------------------------------------------------
__global__ void place_kernel(const void* __restrict__ eidx_raw,
                             const float* __restrict__ eattr,
                             const float* __restrict__ emlp_w,
                             const float* __restrict__ emlp_b,
                             int E)
{
    int e = blockIdx.x * blockDim.x + threadIdx.x;
    if (e >= E) return;

    int s, d;
    if (g_is64) {
        const long long* p = (const long long*)eidx_raw;
        s = (int)p[e];
        d = (int)p[(size_t)E + e];
    } else {
        const int* p = (const int*)eidx_raw;
        s = p[e];
        d = p[(size_t)E + e];
    }

    const float4 a0 = *(const float4*)(eattr + (size_t)e * 8);
    const float4 a1 = *(const float4*)(eattr + (size_t)e * 8 + 4);

    float sp[NL];
#pragma unroll
    for (int l = 0; l < NL; l++) {
        const float* wp = emlp_w + l * 8;
        float z = emlp_b[l];
        z = fmaf(a0.x, wp[0], z);
        z = fmaf(a0.y, wp[1], z);
        z = fmaf(a0.z, wp[2], z);
        z = fmaf(a0.w, wp[3], z);
        z = fmaf(a1.x, wp[4], z);
        z = fmaf(a1.y, wp[5], z);
        z = fmaf(a1.z, wp[6], z);
        z = fmaf(a1.w, wp[7], z);
        sp[l] = fmaxf(z, 0.f) + log1pf(expf(-fabsf(z)));
    }

    int pos = atomicAdd(&g_cur[d], 1);
    g_edges[pos] = make_float4(__int_as_float(s), sp[0], sp[1], sp[2]);
}

// ---------------------------------------------------------------------------
__device__ __forceinline__ void cvt_fma8(float* acc, uint4 u, float w)
{
    float2 p;
    p = __bfloat1622float2(*reinterpret_cast<__nv_bfloat162*>(&u.x));
    acc[0] = fmaf(w, p.x, acc[0]); acc[1] = fmaf(w, p.y, acc[1]);
    p = __bfloat1622float2(*reinterpret_cast<__nv_bfloat162*>(&u.y));
    acc[2] = fmaf(w, p.x, acc[2]); acc[3] = fmaf(w, p.y, acc[3]);
    p = __bfloat1622float2(*reinterpret_cast<__nv_bfloat162*>(&u.z));
    acc[4] = fmaf(w, p.x, acc[4]); acc[5] = fmaf(w, p.y, acc[5]);
    p = __bfloat1622float2(*reinterpret_cast<__nv_bfloat162*>(&u.w));
    acc[6] = fmaf(w, p.x, acc[6]); acc[7] = fmaf(w, p.y, acc[7]);
}

// ---------------------------------------------------------------------------
// Gather kernel. Warp per node r; 16 edges/warp-pass (MLP=4 per quarter).
// Single accumulator set (8 interleaved FMA chains give ILP >= pipe need);
// minBlocksPerMultiprocessor=5 caps regs (~51) for 40 warps/SM latency cover.
// Writes corrected activation a = sum w*h_b[src] - (sum w)*h[r] to ga.
// ---------------------------------------------------------------------------
template <int L>
__global__ void __launch_bounds__(256, 5)
gather_kernel(const float* __restrict__ hin,
              const __nv_bfloat16* __restrict__ hin_b,
              float* __restrict__ ga, int N)
{
    const int warp = threadIdx.x >> 5;
    const int lane = threadIdx.x & 31;
    const int f8      = lane & 7;
    const int quarter = lane >> 3;
    const int warps_per_grid = (blockDim.x >> 5) * gridDim.x;

    for (int r = blockIdx.x * (blockDim.x >> 5) + warp; r < N; r += warps_per_grid) {
        const int start = __ldg(g_offs + r);
        const int end   = __ldg(g_offs + r + 1);

        float acc[8] = {0.f, 0.f, 0.f, 0.f, 0.f, 0.f, 0.f, 0.f};
        float cw = 0.f;

        int i = start + quarter;
        for (; i + 12 < end; i += 16) {
            float4 r0 = __ldg(g_edges + i);
            float4 r1 = __ldg(g_edges + i + 4);
            float4 r2 = __ldg(g_edges + i + 8);
            float4 r3 = __ldg(g_edges + i + 12);
            uint4 u0 = __ldg((const uint4*)(hin_b + (size_t)__float_as_int(r0.x) * D) + f8);
            uint4 u1 = __ldg((const uint4*)(hin_b + (size_t)__float_as_int(r1.x) * D) + f8);
            uint4 u2 = __ldg((const uint4*)(hin_b + (size_t)__float_as_int(r2.x) * D) + f8);
            uint4 u3 = __ldg((const uint4*)(hin_b + (size_t)__float_as_int(r3.x) * D) + f8);
            float w0 = (L == 0) ? r0.y : (L == 1) ? r0.z : r0.w;
            float w1 = (L == 0) ? r1.y : (L == 1) ? r1.z : r1.w;
            float w2 = (L == 0) ? r2.y : (L == 1) ? r2.z : r2.w;
            float w3 = (L == 0) ? r3.y : (L == 1) ? r3.z : r3.w;
            cvt_fma8(acc, u0, w0); cw += w0;
            cvt_fma8(acc, u1, w1); cw += w1;
            cvt_fma8(acc, u2, w2); cw += w2;
            cvt_fma8(acc, u3, w3); cw += w3;
        }
        for (; i < end; i += 4) {
            float4 re = __ldg(g_edges + i);
            float we = (L == 0) ? re.y : (L == 1) ? re.z : re.w;
            uint4 u = __ldg((const uint4*)(hin_b + (size_t)__float_as_int(re.x) * D) + f8);
            cvt_fma8(acc, u, we); cw += we;
        }

#pragma unroll
        for (int j = 0; j < 8; j++) {
            acc[j] += __shfl_xor_sync(0xffffffffu, acc[j], 8);
            acc[j] += __shfl_xor_sync(0xffffffffu, acc[j], 16);
        }
#pragma unroll
        for (int o = 16; o > 0; o >>= 1)
            cw += __shfl_xor_sync(0xffffffffu, cw, o);
        cw *= (1.f / 8.f);

        if (lane < 8) {
            const float* hr = hin + (size_t)r * D + f8 * 8;
            float4 h0 = *(const float4*)hr;
            float4 h1 = *(const float4*)(hr + 4);
            float4 o0 = make_float4(acc[0] - cw * h0.x, acc[1] - cw * h0.y,
                                    acc[2] - cw * h0.z, acc[3] - cw * h0.w);
            float4 o1 = make_float4(acc[4] - cw * h1.x, acc[5] - cw * h1.y,
                                    acc[6] - cw * h1.z, acc[7] - cw * h1.w);
            float* gp = ga + (size_t)r * D + f8 * 8;
            *(float4*)gp       = o0;
            *(float4*)(gp + 4) = o1;
        }
    }
}

// ---------------------------------------------------------------------------
// Node-update kernel: register-tiled GEMM over 64-node tiles (unchanged R13).
// ---------------------------------------------------------------------------
template <bool FUSE_FC>
__global__ void __launch_bounds__(256)
nodeupdate_kernel(const float* __restrict__ ga,
                  const float* __restrict__ hin,
                  float* __restrict__ hout,
                  __nv_bfloat16* __restrict__ hout_b,   // null if FUSE_FC
                  const float* __restrict__ W,
                  const float* __restrict__ bias,
                  const float* __restrict__ gamma,
                  const float* __restrict__ beta,
                  const float* __restrict__ fcW,
                  const float* __restrict__ fcb,
                  int N)
{
    __shared__ float sAT[D][72];
    __shared__ float sWT[D][68];
    __shared__ float sred[D][34];
    __shared__ float smu[D], sinv[D];
    __shared__ float sb[D], sg[D], sbt[D], sfb[D];

    const int tid = threadIdx.x;

    for (int i = tid; i < D * D; i += 256) {
        int row = i >> 6, k = i & 63;
        sWT[k][row] = W[i];
    }
    if (tid < D) {
        sb[tid]  = bias[tid];
        sg[tid]  = gamma[tid];
        sbt[tid] = beta[tid];
        if (FUSE_FC) sfb[tid] = fcb[tid];
    }

    const int base = blockIdx.x * 64;
    {
        int node_l = tid >> 2, kq = tid & 3;
        int node = base + node_l;
#pragma unroll
        for (int q = 0; q < 4; q++) {
            int k0 = kq * 16 + q * 4;
            float4 v = make_float4(0.f, 0.f, 0.f, 0.f);
            if (node < N) v = *(const float4*)(ga + (size_t)node * D + k0);
            sAT[k0][node_l]     = v.x;
            sAT[k0 + 1][node_l] = v.y;
            sAT[k0 + 2][node_l] = v.z;
            sAT[k0 + 3][node_l] = v.w;
        }
    }
    __syncthreads();

    const int tn = tid & 15, tc = tid >> 4;

    float acc[4][4] = {};
#pragma unroll
    for (int k = 0; k < D; k++) {
        float4 a4 = *(const float4*)&sAT[k][tn * 4];
        float4 w4 = *(const float4*)&sWT[k][tc * 4];
        float aa[4] = {a4.x, a4.y, a4.z, a4.w};
        float ww[4] = {w4.x, w4.y, w4.z, w4.w};
#pragma unroll
        for (int ni = 0; ni < 4; ni++)
#pragma unroll
            for (int ci = 0; ci < 4; ci++)
                acc[ni][ci] = fmaf(aa[ni], ww[ci], acc[ni][ci]);
    }

    float h[4][4];
#pragma unroll
    for (int ni = 0; ni < 4; ni++) {
        float s = 0.f, sq = 0.f;
#pragma unroll
        for (int ci = 0; ci < 4; ci++) {
            float v = fmaxf(acc[ni][ci] + sb[tc * 4 + ci], 0.f);
            h[ni][ci] = v;
            s += v;
            sq += v * v;
        }
        sred[tn * 4 + ni][tc]      = s;
        sred[tn * 4 + ni][17 + tc] = sq;
    }
    __syncthreads();

    if (tid < 64) {
        float s = 0.f, sq = 0.f;
#pragma unroll
        for (int j = 0; j < 16; j++) {
            s  += sred[tid][j];
            sq += sred[tid][17 + j];
        }
        float mu  = s * (1.f / D);
        float var = sq * (1.f / D) - mu * mu;
        smu[tid]  = mu;
        sinv[tid] = rsqrtf(var + 1e-5f);
    }
    __syncthreads();

    float o[4][4];
#pragma unroll
    for (int ni = 0; ni < 4; ni++) {
        int node = base + tn * 4 + ni;
        float4 hi = make_float4(0.f, 0.f, 0.f, 0.f);
        if (node < N) hi = *(const float4*)(hin + (size_t)node * D + tc * 4);
        float hiv[4] = {hi.x, hi.y, hi.z, hi.w};
        float mu  = smu[tn * 4 + ni];
        float inv = sinv[tn * 4 + ni];
#pragma unroll
        for (int ci = 0; ci < 4; ci++) {
            int col = tc * 4 + ci;
            o[ni][ci] = (h[ni][ci] - mu) * inv * sg[col] + sbt[col] + hiv[ci];
        }
    }

    if (!FUSE_FC) {
#pragma unroll
        for (int ni = 0; ni < 4; ni++) {
            int node = base + tn * 4 + ni;
            if (node < N) {
                float* hp = hout + (size_t)node * D + tc * 4;
                *(float4*)hp = make_float4(o[ni][0], o[ni][1], o[ni][2], o[ni][3]);
                __nv_bfloat16* bp = hout_b + (size_t)node * D + tc * 4;
                *(__nv_bfloat162*)bp       = __floats2bfloat162_rn(o[ni][0], o[ni][1]);
                *(__nv_bfloat162*)(bp + 2) = __floats2bfloat162_rn(o[ni][2], o[ni][3]);
            }
        }
    } else {
        for (int i = tid; i < D * D; i += 256) {
            int row = i >> 6, k = i & 63;
            sWT[k][row] = fcW[i];
        }
#pragma unroll
        for (int ni = 0; ni < 4; ni++)
#pragma unroll
            for (int ci = 0; ci < 4; ci++)
                sAT[tc * 4 + ci][tn * 4 + ni] = o[ni][ci];
        __syncthreads();

        float f[4][4] = {};
#pragma unroll
        for (int k = 0; k < D; k++) {
            float4 a4 = *(const float4*)&sAT[k][tn * 4];
            float4 w4 = *(const float4*)&sWT[k][tc * 4];
            float aa[4] = {a4.x, a4.y, a4.z, a4.w};
            float ww[4] = {w4.x, w4.y, w4.z, w4.w};
#pragma unroll
            for (int ni = 0; ni < 4; ni++)
#pragma unroll
                for (int ci = 0; ci < 4; ci++)
                    f[ni][ci] = fmaf(aa[ni], ww[ci], f[ni][ci]);
        }
#pragma unroll
        for (int ni = 0; ni < 4; ni++) {
            int node = base + tn * 4 + ni;
            if (node < N) {
                float* hp = hout + (size_t)node * D + tc * 4;
                *(float4*)hp = make_float4(f[ni][0] + sfb[tc * 4 + 0],
                                           f[ni][1] + sfb[tc * 4 + 1],
                                           f[ni][2] + sfb[tc * 4 + 2],
                                           f[ni][3] + sfb[tc * 4 + 3]);
            }
        }
    }
}

// ---------------------------------------------------------------------------
extern "C" void kernel_launch(void* const* d_in, const int* in_sizes, int n_in,
                              void* d_out, int out_size)
{
    const float* x      = (const float*)d_in[0];
    const void*  eidx   = d_in[1];
    const float* eattr  = (const float*)d_in[2];
    const float* lin_w  = (const float*)d_in[3];
    const float* lin_b  = (const float*)d_in[4];
    const float* emlp_w = (const float*)d_in[5];
    const float* emlp_b = (const float*)d_in[6];
    const float* gamma  = (const float*)d_in[7];
    const float* beta   = (const float*)d_in[8];
    const float* fc_w   = (const float*)d_in[9];
    const float* fc_b   = (const float*)d_in[10];
    float*       out    = (float*)d_out;

    const int E = in_sizes[1] / 2;
    const int N = in_sizes[0] / D;

    float *hA, *hB, *ga;
    __nv_bfloat16 *xb, *hbA, *hbB;
    cudaGetSymbolAddress((void**)&hA,  g_hA);
    cudaGetSymbolAddress((void**)&hB,  g_hB);
    cudaGetSymbolAddress((void**)&ga,  g_ga);
    cudaGetSymbolAddress((void**)&xb,  g_xb);
    cudaGetSymbolAddress((void**)&hbA, g_hbA);
    cudaGetSymbolAddress((void**)&hbB, g_hbB);

    // --- build ---
    const int NB = (N + SCAN_B - 1) / SCAN_B;
    const int nfeat = N * D;
    const int init_blocks = (nfeat / 4 + 255) / 256;
    init_kernel<<<init_blocks, 256>>>((const int*)eidx, x, xb, N, nfeat);
    hist_kernel<<<(E + 255) / 256, 256>>>(eidx, E);
    scan_phase1<<<NB, SCAN_B>>>(N);
    scan_phase2<<<1, 1024>>>(NB);
    scan_phase3<<<NB, SCAN_B>>>(N);
    place_kernel<<<(E + 255) / 256, 256>>>(eidx, eattr, emlp_w, emlp_b, E);

    // --- layers: gather -> tiled GEMM/LN/residual ---
    const int gblocks = 2960, gthreads = 256;
    const int tblocks = (N + 63) / 64;

    gather_kernel<0><<<gblocks, gthreads>>>(x, xb, ga, N);
    nodeupdate_kernel<false><<<tblocks, 256>>>(ga, x, hA, hbA,
                                               lin_w, lin_b, gamma, beta,
                                               nullptr, nullptr, N);

    gather_kernel<1><<<gblocks, gthreads>>>(hA, hbA, ga, N);
    nodeupdate_kernel<false><<<tblocks, 256>>>(ga, hA, hB, hbB,
                                               lin_w + (size_t)D * D, lin_b + D,
                                               gamma + D, beta + D,
                                               nullptr, nullptr, N);

    gather_kernel<2><<<gblocks, gthreads>>>(hB, hbB, ga, N);
    nodeupdate_kernel<true><<<tblocks, 256>>>(ga, hB, out, nullptr,
                                              lin_w + (size_t)2 * D * D, lin_b + 2 * D,
                                              gamma + 2 * D, beta + 2 * D,
                                              fc_w, fc_b, N);
}

// round 16
// speedup vs baseline: 1.2231x; 1.0178x over previous
#include <cuda_runtime.h>
#include <cuda_bf16.h>
#include <math.h>

#define N_NODES_MAX 100000
#define N_EDGES_MAX 3200000
#define D 64
#define NL 3
#define SCAN_B 256
#define MAX_NB ((N_NODES_MAX + SCAN_B - 1) / SCAN_B + 1)

// ---- device scratch (no allocation allowed). 256B-aligned for vector loads. ----
__device__ __align__(256) float4 g_edges[N_EDGES_MAX];   // {src, w_l0, w_l1, w_l2}
__device__ __align__(256) int   g_deg[N_NODES_MAX];
__device__ __align__(256) int   g_offs[N_NODES_MAX + 1];
__device__ __align__(256) int   g_cur[N_NODES_MAX];
__device__ __align__(256) int   g_bsum[MAX_NB];
__device__ __align__(256) int   g_boff[MAX_NB];
__device__ __align__(256) float g_ga[(size_t)N_NODES_MAX * D];   // corrected activations
__device__ __align__(256) float g_hA[(size_t)N_NODES_MAX * D];
__device__ __align__(256) float g_hB[(size_t)N_NODES_MAX * D];
__device__ __align__(256) __nv_bfloat16 g_xb [(size_t)N_NODES_MAX * D];
__device__ __align__(256) __nv_bfloat16 g_hbA[(size_t)N_NODES_MAX * D];
__device__ __align__(256) __nv_bfloat16 g_hbB[(size_t)N_NODES_MAX * D];
__device__ int g_is64;

// ---------------------------------------------------------------------------
// Kernel 1: init — zero deg; convert x -> bf16 shadow; block 0 probes dtype.
// ---------------------------------------------------------------------------
__global__ void init_kernel(const int* __restrict__ w32,
                            const float* __restrict__ x,
                            __nv_bfloat16* __restrict__ xb,
                            int N, int nfeat)
{
    int i = blockIdx.x * blockDim.x + threadIdx.x;
    if (i < N) g_deg[i] = 0;

    int idx = i * 4;
    if (idx < nfeat) {
        float4 v = *(const float4*)(x + idx);
        *(__nv_bfloat162*)(xb + idx)     = __floats2bfloat162_rn(v.x, v.y);
        *(__nv_bfloat162*)(xb + idx + 2) = __floats2bfloat162_rn(v.z, v.w);
    }

    if (blockIdx.x == 0) {
        __shared__ int any;
        if (threadIdx.x == 0) any = 0;
        __syncthreads();
        int acc = 0;
        for (int k = threadIdx.x * 2 + 1; k < 4096; k += blockDim.x * 2)
            acc |= w32[k];
        if (acc) atomicOr(&any, 1);
        __syncthreads();
        if (threadIdx.x == 0) g_is64 = (any == 0) ? 1 : 0;
    }
}

// ---------------------------------------------------------------------------
__global__ void hist_kernel(const void* __restrict__ eidx_raw, int E)
{
    int e = blockIdx.x * blockDim.x + threadIdx.x;
    if (e >= E) return;
    int d;
    if (g_is64) d = (int)((const long long*)eidx_raw)[(size_t)E + e];
    else        d = ((const int*)eidx_raw)[(size_t)E + e];
    atomicAdd(&g_deg[d], 1);
}

// ---------------------------------------------------------------------------
__global__ void scan_phase1(int N)
{
    __shared__ int sh[SCAN_B];
    const int tid = threadIdx.x;
    const int i = blockIdx.x * SCAN_B + tid;
    int v = (i < N) ? g_deg[i] : 0;
    sh[tid] = v;
    __syncthreads();
    for (int off = 1; off < SCAN_B; off <<= 1) {
        int a = sh[tid];
        int b = (tid >= off) ? sh[tid - off] : 0;
        __syncthreads();
        sh[tid] = a + b;
        __syncthreads();
    }
    if (i < N) g_offs[i] = sh[tid] - v;
    if (tid == SCAN_B - 1) g_bsum[blockIdx.x] = sh[SCAN_B - 1];
}

__global__ void scan_phase2(int NB)
{
    __shared__ int sh[1024];
    const int tid = threadIdx.x;
    int v = (tid < NB) ? g_bsum[tid] : 0;
    sh[tid] = v;
    __syncthreads();
    for (int off = 1; off < 1024; off <<= 1) {
        int a = sh[tid];
        int b = (tid >= off) ? sh[tid - off] : 0;
        __syncthreads();
        sh[tid] = a + b;
        __syncthreads();
    }
    if (tid < NB) g_boff[tid] = sh[tid] - v;
}

__global__ void scan_phase3(int N)
{
    const int i = blockIdx.x * SCAN_B + threadIdx.x;
    if (i < N) {
        int o = g_offs[i] + g_boff[blockIdx.x];
        g_offs[i] = o;
        g_cur[i]  = o;
        if (i == N - 1) g_offs[N] = o + g_deg[i];
    }
}

// ---------------------------------------------------------------------------
__global__ void place_kernel(const void* __restrict__ eidx_raw,
                             const float* __restrict__ eattr,
                             const float* __restrict__ emlp_w,
                             const float* __restrict__ emlp_b,
                             int E)
{
    int e = blockIdx.x * blockDim.x + threadIdx.x;
    if (e >= E) return;

    int s, d;
    if (g_is64) {
        const long long* p = (const long long*)eidx_raw;
        s = (int)p[e];
        d = (int)p[(size_t)E + e];
    } else {
        const int* p = (const int*)eidx_raw;
        s = p[e];
        d = p[(size_t)E + e];
    }

    const float4 a0 = *(const float4*)(eattr + (size_t)e * 8);
    const float4 a1 = *(const float4*)(eattr + (size_t)e * 8 + 4);

    float sp[NL];
#pragma unroll
    for (int l = 0; l < NL; l++) {
        const float* wp = emlp_w + l * 8;
        float z = emlp_b[l];
        z = fmaf(a0.x, wp[0], z);
        z = fmaf(a0.y, wp[1], z);
        z = fmaf(a0.z, wp[2], z);
        z = fmaf(a0.w, wp[3], z);
        z = fmaf(a1.x, wp[4], z);
        z = fmaf(a1.y, wp[5], z);
        z = fmaf(a1.z, wp[6], z);
        z = fmaf(a1.w, wp[7], z);
        sp[l] = fmaxf(z, 0.f) + log1pf(expf(-fabsf(z)));
    }

    int pos = atomicAdd(&g_cur[d], 1);
    g_edges[pos] = make_float4(__int_as_float(s), sp[0], sp[1], sp[2]);
}

// ---------------------------------------------------------------------------
__device__ __forceinline__ void cvt_fma8(float* acc, uint4 u, float w)
{
    float2 p;
    p = __bfloat1622float2(*reinterpret_cast<__nv_bfloat162*>(&u.x));
    acc[0] = fmaf(w, p.x, acc[0]); acc[1] = fmaf(w, p.y, acc[1]);
    p = __bfloat1622float2(*reinterpret_cast<__nv_bfloat162*>(&u.y));
    acc[2] = fmaf(w, p.x, acc[2]); acc[3] = fmaf(w, p.y, acc[3]);
    p = __bfloat1622float2(*reinterpret_cast<__nv_bfloat162*>(&u.z));
    acc[4] = fmaf(w, p.x, acc[4]); acc[5] = fmaf(w, p.y, acc[5]);
    p = __bfloat1622float2(*reinterpret_cast<__nv_bfloat162*>(&u.w));
    acc[6] = fmaf(w, p.x, acc[6]); acc[7] = fmaf(w, p.y, acc[7]);
}

// ---------------------------------------------------------------------------
// Gather kernel. Warp per node r; FULLY PREDICATED 16-edge passes: every
// edge (including the tail) is loaded at MLP=4. Invalid slots read a safe
// address (start) with weight forced to 0.
// ---------------------------------------------------------------------------
template <int L>
__global__ void __launch_bounds__(256, 5)
gather_kernel(const float* __restrict__ hin,
              const __nv_bfloat16* __restrict__ hin_b,
              float* __restrict__ ga, int N)
{
    const int warp = threadIdx.x >> 5;
    const int lane = threadIdx.x & 31;
    const int f8      = lane & 7;
    const int quarter = lane >> 3;
    const int warps_per_grid = (blockDim.x >> 5) * gridDim.x;

    for (int r = blockIdx.x * (blockDim.x >> 5) + warp; r < N; r += warps_per_grid) {
        const int start = __ldg(g_offs + r);
        const int end   = __ldg(g_offs + r + 1);

        float acc[8] = {0.f, 0.f, 0.f, 0.f, 0.f, 0.f, 0.f, 0.f};
        float cw = 0.f;

        for (int i = start + quarter; i < end; i += 16) {
            int i1 = i + 4, i2 = i + 8, i3 = i + 12;
            bool v1 = i1 < end, v2 = i2 < end, v3 = i3 < end;
            int o1 = v1 ? i1 : start;
            int o2 = v2 ? i2 : start;
            int o3 = v3 ? i3 : start;

            float4 r0 = __ldg(g_edges + i);
            float4 r1 = __ldg(g_edges + o1);
            float4 r2 = __ldg(g_edges + o2);
            float4 r3 = __ldg(g_edges + o3);
            uint4 u0 = __ldg((const uint4*)(hin_b + (size_t)__float_as_int(r0.x) * D) + f8);
            uint4 u1 = __ldg((const uint4*)(hin_b + (size_t)__float_as_int(r1.x) * D) + f8);
            uint4 u2 = __ldg((const uint4*)(hin_b + (size_t)__float_as_int(r2.x) * D) + f8);
            uint4 u3 = __ldg((const uint4*)(hin_b + (size_t)__float_as_int(r3.x) * D) + f8);

            float w0 = (L == 0) ? r0.y : (L == 1) ? r0.z : r0.w;
            float w1 = (L == 0) ? r1.y : (L == 1) ? r1.z : r1.w;
            float w2 = (L == 0) ? r2.y : (L == 1) ? r2.z : r2.w;
            float w3 = (L == 0) ? r3.y : (L == 1) ? r3.z : r3.w;
            w1 = v1 ? w1 : 0.f;
            w2 = v2 ? w2 : 0.f;
            w3 = v3 ? w3 : 0.f;

            cvt_fma8(acc, u0, w0); cw += w0;
            cvt_fma8(acc, u1, w1); cw += w1;
            cvt_fma8(acc, u2, w2); cw += w2;
            cvt_fma8(acc, u3, w3); cw += w3;
        }

#pragma unroll
        for (int j = 0; j < 8; j++) {
            acc[j] += __shfl_xor_sync(0xffffffffu, acc[j], 8);
            acc[j] += __shfl_xor_sync(0xffffffffu, acc[j], 16);
        }
#pragma unroll
        for (int o = 16; o > 0; o >>= 1)
            cw += __shfl_xor_sync(0xffffffffu, cw, o);
        cw *= (1.f / 8.f);

        if (lane < 8) {
            const float* hr = hin + (size_t)r * D + f8 * 8;
            float4 h0 = *(const float4*)hr;
            float4 h1 = *(const float4*)(hr + 4);
            float4 o0 = make_float4(acc[0] - cw * h0.x, acc[1] - cw * h0.y,
                                    acc[2] - cw * h0.z, acc[3] - cw * h0.w);
            float4 o1 = make_float4(acc[4] - cw * h1.x, acc[5] - cw * h1.y,
                                    acc[6] - cw * h1.z, acc[7] - cw * h1.w);
            float* gp = ga + (size_t)r * D + f8 * 8;
            *(float4*)gp       = o0;
            *(float4*)(gp + 4) = o1;
        }
    }
}

// ---------------------------------------------------------------------------
// Node-update kernel: register-tiled GEMM over 64-node tiles (unchanged).
// ---------------------------------------------------------------------------
template <bool FUSE_FC>
__global__ void __launch_bounds__(256)
nodeupdate_kernel(const float* __restrict__ ga,
                  const float* __restrict__ hin,
                  float* __restrict__ hout,
                  __nv_bfloat16* __restrict__ hout_b,   // null if FUSE_FC
                  const float* __restrict__ W,
                  const float* __restrict__ bias,
                  const float* __restrict__ gamma,
                  const float* __restrict__ beta,
                  const float* __restrict__ fcW,
                  const float* __restrict__ fcb,
                  int N)
{
    __shared__ float sAT[D][72];
    __shared__ float sWT[D][68];
    __shared__ float sred[D][34];
    __shared__ float smu[D], sinv[D];
    __shared__ float sb[D], sg[D], sbt[D], sfb[D];

    const int tid = threadIdx.x;

    for (int i = tid; i < D * D; i += 256) {
        int row = i >> 6, k = i & 63;
        sWT[k][row] = W[i];
    }
    if (tid < D) {
        sb[tid]  = bias[tid];
        sg[tid]  = gamma[tid];
        sbt[tid] = beta[tid];
        if (FUSE_FC) sfb[tid] = fcb[tid];
    }

    const int base = blockIdx.x * 64;
    {
        int node_l = tid >> 2, kq = tid & 3;
        int node = base + node_l;
#pragma unroll
        for (int q = 0; q < 4; q++) {
            int k0 = kq * 16 + q * 4;
            float4 v = make_float4(0.f, 0.f, 0.f, 0.f);
            if (node < N) v = *(const float4*)(ga + (size_t)node * D + k0);
            sAT[k0][node_l]     = v.x;
            sAT[k0 + 1][node_l] = v.y;
            sAT[k0 + 2][node_l] = v.z;
            sAT[k0 + 3][node_l] = v.w;
        }
    }
    __syncthreads();

    const int tn = tid & 15, tc = tid >> 4;

    float acc[4][4] = {};
#pragma unroll
    for (int k = 0; k < D; k++) {
        float4 a4 = *(const float4*)&sAT[k][tn * 4];
        float4 w4 = *(const float4*)&sWT[k][tc * 4];
        float aa[4] = {a4.x, a4.y, a4.z, a4.w};
        float ww[4] = {w4.x, w4.y, w4.z, w4.w};
#pragma unroll
        for (int ni = 0; ni < 4; ni++)
#pragma unroll
            for (int ci = 0; ci < 4; ci++)
                acc[ni][ci] = fmaf(aa[ni], ww[ci], acc[ni][ci]);
    }

    float h[4][4];
#pragma unroll
    for (int ni = 0; ni < 4; ni++) {
        float s = 0.f, sq = 0.f;
#pragma unroll
        for (int ci = 0; ci < 4; ci++) {
            float v = fmaxf(acc[ni][ci] + sb[tc * 4 + ci], 0.f);
            h[ni][ci] = v;
            s += v;
            sq += v * v;
        }
        sred[tn * 4 + ni][tc]      = s;
        sred[tn * 4 + ni][17 + tc] = sq;
    }
    __syncthreads();

    if (tid < 64) {
        float s = 0.f, sq = 0.f;
#pragma unroll
        for (int j = 0; j < 16; j++) {
            s  += sred[tid][j];
            sq += sred[tid][17 + j];
        }
        float mu  = s * (1.f / D);
        float var = sq * (1.f / D) - mu * mu;
        smu[tid]  = mu;
        sinv[tid] = rsqrtf(var + 1e-5f);
    }
    __syncthreads();

    float o[4][4];
#pragma unroll
    for (int ni = 0; ni < 4; ni++) {
        int node = base + tn * 4 + ni;
        float4 hi = make_float4(0.f, 0.f, 0.f, 0.f);
        if (node < N) hi = *(const float4*)(hin + (size_t)node * D + tc * 4);
        float hiv[4] = {hi.x, hi.y, hi.z, hi.w};
        float mu  = smu[tn * 4 + ni];
        float inv = sinv[tn * 4 + ni];
#pragma unroll
        for (int ci = 0; ci < 4; ci++) {
            int col = tc * 4 + ci;
            o[ni][ci] = (h[ni][ci] - mu) * inv * sg[col] + sbt[col] + hiv[ci];
        }
    }

    if (!FUSE_FC) {
#pragma unroll
        for (int ni = 0; ni < 4; ni++) {
            int node = base + tn * 4 + ni;
            if (node < N) {
                float* hp = hout + (size_t)node * D + tc * 4;
                *(float4*)hp = make_float4(o[ni][0], o[ni][1], o[ni][2], o[ni][3]);
                __nv_bfloat16* bp = hout_b + (size_t)node * D + tc * 4;
                *(__nv_bfloat162*)bp       = __floats2bfloat162_rn(o[ni][0], o[ni][1]);
                *(__nv_bfloat162*)(bp + 2) = __floats2bfloat162_rn(o[ni][2], o[ni][3]);
            }
        }
    } else {
        for (int i = tid; i < D * D; i += 256) {
            int row = i >> 6, k = i & 63;
            sWT[k][row] = fcW[i];
        }
#pragma unroll
        for (int ni = 0; ni < 4; ni++)
#pragma unroll
            for (int ci = 0; ci < 4; ci++)
                sAT[tc * 4 + ci][tn * 4 + ni] = o[ni][ci];
        __syncthreads();

        float f[4][4] = {};
#pragma unroll
        for (int k = 0; k < D; k++) {
            float4 a4 = *(const float4*)&sAT[k][tn * 4];
            float4 w4 = *(const float4*)&sWT[k][tc * 4];
            float aa[4] = {a4.x, a4.y, a4.z, a4.w};
            float ww[4] = {w4.x, w4.y, w4.z, w4.w};
#pragma unroll
            for (int ni = 0; ni < 4; ni++)
#pragma unroll
                for (int ci = 0; ci < 4; ci++)
                    f[ni][ci] = fmaf(aa[ni], ww[ci], f[ni][ci]);
        }
#pragma unroll
        for (int ni = 0; ni < 4; ni++) {
            int node = base + tn * 4 + ni;
            if (node < N) {
                float* hp = hout + (size_t)node * D + tc * 4;
                *(float4*)hp = make_float4(f[ni][0] + sfb[tc * 4 + 0],
                                           f[ni][1] + sfb[tc * 4 + 1],
                                           f[ni][2] + sfb[tc * 4 + 2],
                                           f[ni][3] + sfb[tc * 4 + 3]);
            }
        }
    }
}

// ---------------------------------------------------------------------------
extern "C" void kernel_launch(void* const* d_in, const int* in_sizes, int n_in,
                              void* d_out, int out_size)
{
    const float* x      = (const float*)d_in[0];
    const void*  eidx   = d_in[1];
    const float* eattr  = (const float*)d_in[2];
    const float* lin_w  = (const float*)d_in[3];
    const float* lin_b  = (const float*)d_in[4];
    const float* emlp_w = (const float*)d_in[5];
    const float* emlp_b = (const float*)d_in[6];
    const float* gamma  = (const float*)d_in[7];
    const float* beta   = (const float*)d_in[8];
    const float* fc_w   = (const float*)d_in[9];
    const float* fc_b   = (const float*)d_in[10];
    float*       out    = (float*)d_out;

    const int E = in_sizes[1] / 2;
    const int N = in_sizes[0] / D;

    float *hA, *hB, *ga;
    __nv_bfloat16 *xb, *hbA, *hbB;
    cudaGetSymbolAddress((void**)&hA,  g_hA);
    cudaGetSymbolAddress((void**)&hB,  g_hB);
    cudaGetSymbolAddress((void**)&ga,  g_ga);
    cudaGetSymbolAddress((void**)&xb,  g_xb);
    cudaGetSymbolAddress((void**)&hbA, g_hbA);
    cudaGetSymbolAddress((void**)&hbB, g_hbB);

    // --- build ---
    const int NB = (N + SCAN_B - 1) / SCAN_B;
    const int nfeat = N * D;
    const int init_blocks = (nfeat / 4 + 255) / 256;
    init_kernel<<<init_blocks, 256>>>((const int*)eidx, x, xb, N, nfeat);
    hist_kernel<<<(E + 255) / 256, 256>>>(eidx, E);
    scan_phase1<<<NB, SCAN_B>>>(N);
    scan_phase2<<<1, 1024>>>(NB);
    scan_phase3<<<NB, SCAN_B>>>(N);
    place_kernel<<<(E + 255) / 256, 256>>>(eidx, eattr, emlp_w, emlp_b, E);

    // --- layers: gather -> tiled GEMM/LN/residual ---
    const int gblocks = 2960, gthreads = 256;
    const int tblocks = (N + 63) / 64;

    gather_kernel<0><<<gblocks, gthreads>>>(x, xb, ga, N);
    nodeupdate_kernel<false><<<tblocks, 256>>>(ga, x, hA, hbA,
                                               lin_w, lin_b, gamma, beta,
                                               nullptr, nullptr, N);

    gather_kernel<1><<<gblocks, gthreads>>>(hA, hbA, ga, N);
    nodeupdate_kernel<false><<<tblocks, 256>>>(ga, hA, hB, hbB,
                                               lin_w + (size_t)D * D, lin_b + D,
                                               gamma + D, beta + D,
                                               nullptr, nullptr, N);

    gather_kernel<2><<<gblocks, gthreads>>>(hB, hbB, ga, N);
    nodeupdate_kernel<true><<<tblocks, 256>>>(ga, hB, out, nullptr,
                                              lin_w + (size_t)2 * D * D, lin_b + 2 * D,
                                              gamma + 2 * D, beta + 2 * D,
                                              fc_w, fc_b, N);
}